// round 9
// baseline (speedup 1.0000x reference)
#include <cuda_runtime.h>
#include <math.h>
#include <stdint.h>

#define NN 262144
#define NE 1048576
#define NG 8192
#define EPG 128

// ---------------- scratch (sanctioned __device__ globals) ----------------
__device__ float g_A[NG * 1024];
__device__ float g_bufA[(size_t)NN * 312];
__device__ float g_bufB[(size_t)NN * 312];
__device__ float g_pool[NG * 312];
__device__ float g_t512[NG * 512];
__device__ float g_t256[NG * 256];
__device__ float g_g1[NG * 128];
__device__ float g_g2[NG * 128];
__device__ float g_cell[NG * 128];
__device__ float g_xc[NG * 384];

// ---------------- tf32 helpers ----------------
__device__ __forceinline__ uint32_t f2tf(float f) {
    uint32_t u;
    asm("cvt.rna.tf32.f32 %0, %1;" : "=r"(u) : "f"(f));
    return u;
}

__device__ __forceinline__ void mma8(float* c, const uint32_t* a, const uint32_t* b) {
    asm volatile(
        "mma.sync.aligned.m16n8k8.row.col.f32.tf32.tf32.f32 "
        "{%0,%1,%2,%3}, {%4,%5,%6,%7}, {%8,%9}, {%0,%1,%2,%3};"
        : "+f"(c[0]), "+f"(c[1]), "+f"(c[2]), "+f"(c[3])
        : "r"(a[0]), "r"(a[1]), "r"(a[2]), "r"(a[3]), "r"(b[0]), "r"(b[1]));
}

// ---------------- build per-graph normalized adjacency ----------------
__global__ void build_A_kernel(const int* __restrict__ ei, float* __restrict__ A) {
    __shared__ int   deg[32];
    __shared__ float dinv[32];
    __shared__ float cnt[1024];
    int g = blockIdx.x, t = threadIdx.x;
    if (t < 32) deg[t] = 1;
    for (int i = t; i < 1024; i += 128) cnt[i] = 0.f;
    __syncthreads();
    int src = ei[g * EPG + t] & 31;
    int dst = ei[NE + g * EPG + t] & 31;
    atomicAdd(&deg[src], 1);
    __syncthreads();
    if (t < 32) dinv[t] = rsqrtf((float)deg[t]);
    atomicAdd(&cnt[src * 32 + dst], 1.f);
    __syncthreads();
    for (int i = t; i < 1024; i += 128) {
        int r = i >> 5, c = i & 31;
        float v = cnt[i] + (r == c ? 1.f : 0.f);
        A[g * 1024 + i] = v * dinv[r] * dinv[c];
    }
}

// ---------------- tf32x3 GEMM: C = act(X @ W + bias) ----------------
// 128x64 block tile, BK=16, 8 warps (4 along M x 2 along N), warp tile 32x32.
// ACT: 0 none, 1 relu, 2 prelu
template <int ACT>
__global__ void gemm_tf32_kernel(const float* __restrict__ X, const float* __restrict__ W,
                                 const float* __restrict__ bias, float* __restrict__ C,
                                 int N, int K, int M, const float* __restrict__ pa) {
    // strides chosen so fragment lds hits 32 distinct banks (stride % 32 == 8)
    __shared__ uint32_t As_hi[16 * 136], As_lo[16 * 136];
    __shared__ uint32_t Bs_hi[16 * 72],  Bs_lo[16 * 72];
    int tid = threadIdx.x, lane = tid & 31, w = tid >> 5;
    int wm = w & 3, wn = w >> 2;
    int gid = lane >> 2, tig = lane & 3;
    int R0 = blockIdx.y * 128, C0 = blockIdx.x * 64;
    float acc[2][4][4] = {};

    for (int k0 = 0; k0 < K; k0 += 16) {
#pragma unroll
        for (int i = 0; i < 8; i++) {                 // X tile 128x16
            int idx = tid + i * 256;
            int r = idx >> 4, kk = idx & 15;
            int row = R0 + r, k = k0 + kk;
            float v = (row < N && k < K) ? X[(size_t)row * K + k] : 0.f;
            uint32_t hi = f2tf(v);
            As_hi[kk * 136 + r] = hi;
            As_lo[kk * 136 + r] = f2tf(v - __uint_as_float(hi));
        }
#pragma unroll
        for (int i = 0; i < 4; i++) {                 // W tile 16x64
            int idx = tid + i * 256;
            int kk = idx >> 6, m = idx & 63;
            int k = k0 + kk, col = C0 + m;
            float v = (k < K && col < M) ? W[(size_t)k * M + col] : 0.f;
            uint32_t hi = f2tf(v);
            Bs_hi[kk * 72 + m] = hi;
            Bs_lo[kk * 72 + m] = f2tf(v - __uint_as_float(hi));
        }
        __syncthreads();
#pragma unroll
        for (int ks = 0; ks < 16; ks += 8) {
            uint32_t ah[2][4], al[2][4], bh[4][2], bl[4][2];
#pragma unroll
            for (int mt = 0; mt < 2; mt++) {
                int r = wm * 32 + mt * 16 + gid;
                int k = ks + tig;
                ah[mt][0] = As_hi[k * 136 + r];       al[mt][0] = As_lo[k * 136 + r];
                ah[mt][1] = As_hi[k * 136 + r + 8];   al[mt][1] = As_lo[k * 136 + r + 8];
                ah[mt][2] = As_hi[(k + 4) * 136 + r]; al[mt][2] = As_lo[(k + 4) * 136 + r];
                ah[mt][3] = As_hi[(k + 4) * 136 + r + 8]; al[mt][3] = As_lo[(k + 4) * 136 + r + 8];
            }
#pragma unroll
            for (int nt = 0; nt < 4; nt++) {
                int c = wn * 32 + nt * 8 + gid;
                int k = ks + tig;
                bh[nt][0] = Bs_hi[k * 72 + c];        bl[nt][0] = Bs_lo[k * 72 + c];
                bh[nt][1] = Bs_hi[(k + 4) * 72 + c];  bl[nt][1] = Bs_lo[(k + 4) * 72 + c];
            }
#pragma unroll
            for (int mt = 0; mt < 2; mt++)
#pragma unroll
                for (int nt = 0; nt < 4; nt++) {
                    mma8(acc[mt][nt], ah[mt], bh[nt]);
                    mma8(acc[mt][nt], al[mt], bh[nt]);
                    mma8(acc[mt][nt], ah[mt], bl[nt]);
                }
        }
        __syncthreads();
    }

    float alpha = (ACT == 2) ? *pa : 0.f;
#pragma unroll
    for (int mt = 0; mt < 2; mt++) {
#pragma unroll
        for (int nt = 0; nt < 4; nt++) {
            int row = R0 + wm * 32 + mt * 16 + gid;
            int col = C0 + wn * 32 + nt * 8 + 2 * tig;
#pragma unroll
            for (int q = 0; q < 4; q++) {
                int r = row + (q >> 1) * 8;
                int c = col + (q & 1);
                if (r < N && c < M) {
                    float v = acc[mt][nt][q] + (bias ? bias[c] : 0.f);
                    if (ACT == 1) v = fmaxf(v, 0.f);
                    if (ACT == 2) v = (v >= 0.f) ? v : alpha * v;
                    C[(size_t)r * M + c] = v;
                }
            }
        }
    }
}

// ---------------- propagation via tf32x3 mma: P_g = A_g (32x32) @ X_g (32xK) ----------------
// 1 block per graph, 4 warps; each warp owns a 16-col slice of a 64-col chunk.
__global__ void prop_tf32_kernel(const float* __restrict__ A, const float* __restrict__ X,
                                 float* __restrict__ P, int K) {
    __shared__ uint32_t sA_hi[32 * 40], sA_lo[32 * 40];   // [c][r], stride 40 (%32==8)
    __shared__ uint32_t sX_hi[32 * 72], sX_lo[32 * 72];   // [c][f], stride 72 (%32==8)
    int g = blockIdx.x, tid = threadIdx.x, lane = tid & 31, w = tid >> 5;
    int gid = lane >> 2, tig = lane & 3;
    const float* Ag = A + g * 1024;
    for (int i = tid; i < 1024; i += 128) {
        int r = i >> 5, c = i & 31;
        float v = Ag[i];
        uint32_t hi = f2tf(v);
        sA_hi[c * 40 + r] = hi;
        sA_lo[c * 40 + r] = f2tf(v - __uint_as_float(hi));
    }
    const float* Xg = X + (size_t)g * 32 * K;
    float* Pg = P + (size_t)g * 32 * K;
    for (int f0 = 0; f0 < K; f0 += 64) {
        __syncthreads();
        for (int i = tid; i < 2048; i += 128) {
            int c = i >> 6, f = i & 63;
            float v = (f0 + f < K) ? Xg[c * K + f0 + f] : 0.f;
            uint32_t hi = f2tf(v);
            sX_hi[c * 72 + f] = hi;
            sX_lo[c * 72 + f] = f2tf(v - __uint_as_float(hi));
        }
        __syncthreads();
        float acc[2][2][4] = {};
#pragma unroll
        for (int kk = 0; kk < 32; kk += 8) {
            uint32_t ah[2][4], al[2][4], bh[2][2], bl[2][2];
#pragma unroll
            for (int mt = 0; mt < 2; mt++) {
                int r = mt * 16 + gid;
                int k = kk + tig;
                ah[mt][0] = sA_hi[k * 40 + r];        al[mt][0] = sA_lo[k * 40 + r];
                ah[mt][1] = sA_hi[k * 40 + r + 8];    al[mt][1] = sA_lo[k * 40 + r + 8];
                ah[mt][2] = sA_hi[(k + 4) * 40 + r];  al[mt][2] = sA_lo[(k + 4) * 40 + r];
                ah[mt][3] = sA_hi[(k + 4) * 40 + r + 8]; al[mt][3] = sA_lo[(k + 4) * 40 + r + 8];
            }
#pragma unroll
            for (int nt = 0; nt < 2; nt++) {
                int f = w * 16 + nt * 8 + gid;
                int k = kk + tig;
                bh[nt][0] = sX_hi[k * 72 + f];        bl[nt][0] = sX_lo[k * 72 + f];
                bh[nt][1] = sX_hi[(k + 4) * 72 + f];  bl[nt][1] = sX_lo[(k + 4) * 72 + f];
            }
#pragma unroll
            for (int mt = 0; mt < 2; mt++)
#pragma unroll
                for (int nt = 0; nt < 2; nt++) {
                    mma8(acc[mt][nt], ah[mt], bh[nt]);
                    mma8(acc[mt][nt], al[mt], bh[nt]);
                    mma8(acc[mt][nt], ah[mt], bl[nt]);
                }
        }
#pragma unroll
        for (int mt = 0; mt < 2; mt++)
#pragma unroll
            for (int nt = 0; nt < 2; nt++) {
                int row = mt * 16 + gid;
                int f = f0 + w * 16 + nt * 8 + 2 * tig;
#pragma unroll
                for (int q = 0; q < 4; q++) {
                    int r = row + (q >> 1) * 8;
                    int c = f + (q & 1);
                    if (c < K) Pg[(size_t)r * K + c] = acc[mt][nt][q];
                }
            }
    }
}

// ---------------- global max pool over 32 nodes per graph ----------------
__global__ void pool_kernel(const float* __restrict__ H, float* __restrict__ out, int F) {
    int g = blockIdx.x, f = threadIdx.x;
    if (f >= F) return;
    const float* Hg = H + (size_t)g * 32 * F;
    float m = -3.4e38f;
#pragma unroll
    for (int r = 0; r < 32; r++) m = fmaxf(m, Hg[r * F + f]);
    out[g * F + f] = m;
}

// ---------------- concat [g1,g2,c] + L2 normalize row ----------------
__global__ void catnorm_kernel(const float* __restrict__ g1, const float* __restrict__ g2,
                               const float* __restrict__ c, float* __restrict__ xc) {
    int g = blockIdx.x, t = threadIdx.x;
    float v0 = g1[g * 128 + t], v1 = g2[g * 128 + t], v2 = c[g * 128 + t];
    float ps = v0 * v0 + v1 * v1 + v2 * v2;
    __shared__ float red[4];
#pragma unroll
    for (int o = 16; o; o >>= 1) ps += __shfl_xor_sync(0xffffffffu, ps, o);
    if ((t & 31) == 0) red[t >> 5] = ps;
    __syncthreads();
    float tot = red[0] + red[1] + red[2] + red[3];
    float inv = 1.f / fmaxf(sqrtf(tot), 1e-12f);
    xc[g * 384 + t]       = v0 * inv;
    xc[g * 384 + 128 + t] = v1 * inv;
    xc[g * 384 + 256 + t] = v2 * inv;
}

// ---------------- final: sigmoid(x @ Wo + bo) ----------------
__global__ void final_kernel(const float* __restrict__ x, const float* __restrict__ Wo,
                             const float* __restrict__ bo, float* __restrict__ out) {
    int w = (blockIdx.x * blockDim.x + threadIdx.x) >> 5;
    int lane = threadIdx.x & 31;
    if (w >= NG) return;
    float acc = 0.f;
#pragma unroll
    for (int k = lane; k < 128; k += 32) acc = fmaf(x[w * 128 + k], Wo[k], acc);
#pragma unroll
    for (int o = 16; o; o >>= 1) acc += __shfl_xor_sync(0xffffffffu, acc, o);
    if (lane == 0) out[w] = 1.f / (1.f + expf(-(acc + bo[0])));
}

// ---------------- host side ----------------
static void gemm_launch(const float* X, const float* W, const float* bias, float* C,
                        int N, int K, int M, int act, const float* pa) {
    dim3 grid((M + 63) / 64, (N + 127) / 128);
    if (act == 0)      gemm_tf32_kernel<0><<<grid, 256>>>(X, W, bias, C, N, K, M, nullptr);
    else if (act == 1) gemm_tf32_kernel<1><<<grid, 256>>>(X, W, bias, C, N, K, M, nullptr);
    else               gemm_tf32_kernel<2><<<grid, 256>>>(X, W, bias, C, N, K, M, pa);
}

extern "C" void kernel_launch(void* const* d_in, const int* in_sizes, int n_in,
                              void* d_out, int out_size) {
    const float* x1   = (const float*)d_in[0];
    const int*   ei1  = (const int*)d_in[1];
    const float* x2   = (const float*)d_in[2];
    const int*   ei2  = (const int*)d_in[3];
    const float* cell = (const float*)d_in[4];
    const float* W1  = (const float*)d_in[7],  *b1  = (const float*)d_in[8];
    const float* W2  = (const float*)d_in[9],  *b2  = (const float*)d_in[10];
    const float* W3  = (const float*)d_in[11], *b3  = (const float*)d_in[12];
    const float* Wg1 = (const float*)d_in[13], *bg1 = (const float*)d_in[14];
    const float* Wg2 = (const float*)d_in[15], *bg2 = (const float*)d_in[16];
    const float* Wr1 = (const float*)d_in[17], *br1 = (const float*)d_in[18];
    const float* Wr2 = (const float*)d_in[19], *br2 = (const float*)d_in[20];
    const float* Wr3 = (const float*)d_in[21], *br3 = (const float*)d_in[22];
    const float* Wf1 = (const float*)d_in[23], *bf1 = (const float*)d_in[24];
    const float* Wf2 = (const float*)d_in[25], *bf2 = (const float*)d_in[26];
    const float* Wo  = (const float*)d_in[27], *bo  = (const float*)d_in[28];
    const float* pa  = (const float*)d_in[29];
    float* out = (float*)d_out;

    float *A, *bufA, *bufB, *pool, *t512, *t256, *G1, *G2, *Cl, *XC;
    cudaGetSymbolAddress((void**)&A,    g_A);
    cudaGetSymbolAddress((void**)&bufA, g_bufA);
    cudaGetSymbolAddress((void**)&bufB, g_bufB);
    cudaGetSymbolAddress((void**)&pool, g_pool);
    cudaGetSymbolAddress((void**)&t512, g_t512);
    cudaGetSymbolAddress((void**)&t256, g_t256);
    cudaGetSymbolAddress((void**)&G1,   g_g1);
    cudaGetSymbolAddress((void**)&G2,   g_g2);
    cudaGetSymbolAddress((void**)&Cl,   g_cell);
    cudaGetSymbolAddress((void**)&XC,   g_xc);

    for (int d = 0; d < 2; d++) {
        const float* x  = d ? x2 : x1;
        const int*   ei = d ? ei2 : ei1;
        float*       G  = d ? G2 : G1;
        build_A_kernel<<<NG, 128>>>(ei, A);
        // GCN reordered: H = relu((A @ X) @ W + b)
        prop_tf32_kernel<<<NG, 128>>>(A, x, bufA, 78);
        gemm_launch(bufA, W1, b1, bufB, NN, 78, 78, 1, pa);
        prop_tf32_kernel<<<NG, 128>>>(A, bufB, bufA, 78);
        gemm_launch(bufA, W2, b2, bufB, NN, 78, 156, 1, pa);
        prop_tf32_kernel<<<NG, 128>>>(A, bufB, bufA, 156);
        gemm_launch(bufA, W3, b3, bufB, NN, 156, 312, 1, pa);
        pool_kernel<<<NG, 320>>>(bufB, pool, 312);
        gemm_launch(pool, Wg1, bg1, t512, NG, 312, 156, 1, pa);
        gemm_launch(t512, Wg2, bg2, G,    NG, 156, 128, 0, pa);
    }

    // cell-line MLP
    gemm_launch(cell, Wr1, br1, t512, NG, 1000, 512, 1, pa);
    gemm_launch(t512, Wr2, br2, t256, NG, 512,  256, 1, pa);
    gemm_launch(t256, Wr3, br3, Cl,   NG, 256,  128, 0, pa);

    // concat + L2 normalize + fused head
    catnorm_kernel<<<NG, 128>>>(G1, G2, Cl, XC);
    gemm_launch(XC,   Wf1, bf1, t512, NG, 384, 512, 2, pa);
    gemm_launch(t512, Wf2, bf2, t256, NG, 512, 128, 2, pa);
    final_kernel<<<NG / 8, 256>>>(t256, Wo, bo, out);
}

// round 12
// speedup vs baseline: 1.9887x; 1.9887x over previous
#include <cuda_runtime.h>
#include <cuda_fp16.h>
#include <math.h>
#include <stdint.h>

#define NN 262144
#define NE 1048576
#define NG 8192
#define EPG 128
#define GS 20   // smem stride in uint32 pairs; 20 % 32 == 20 -> gid*20+tig distinct mod 32

// ---------------- scratch (sanctioned __device__ globals) ----------------
__device__ float g_A[NG * 1024];
__device__ float g_bufA[(size_t)NN * 312];
__device__ float g_bufB[(size_t)NN * 312];
__device__ float g_pool[NG * 312];
__device__ float g_t512[NG * 512];
__device__ float g_t256[NG * 256];
__device__ float g_g1[NG * 128];
__device__ float g_g2[NG * 128];
__device__ float g_cell[NG * 128];
__device__ float g_xc[NG * 384];

// ---------------- fp16 split helpers ----------------
__device__ __forceinline__ uint32_t pack_hl(float v0, float v1, uint32_t& lo) {
    __half h0 = __float2half_rn(v0), h1 = __float2half_rn(v1);
    __half l0 = __float2half_rn(v0 - __half2float(h0));
    __half l1 = __float2half_rn(v1 - __half2float(h1));
    lo = ((uint32_t)__half_as_ushort(l1) << 16) | __half_as_ushort(l0);
    return ((uint32_t)__half_as_ushort(h1) << 16) | __half_as_ushort(h0);
}

__device__ __forceinline__ void mma16(float* c, const uint32_t* a, const uint32_t* b) {
    asm volatile(
        "mma.sync.aligned.m16n8k16.row.col.f32.f16.f16.f32 "
        "{%0,%1,%2,%3}, {%4,%5,%6,%7}, {%8,%9}, {%0,%1,%2,%3};"
        : "+f"(c[0]), "+f"(c[1]), "+f"(c[2]), "+f"(c[3])
        : "r"(a[0]), "r"(a[1]), "r"(a[2]), "r"(a[3]), "r"(b[0]), "r"(b[1]));
}

// ---------------- build per-graph normalized adjacency ----------------
__global__ void build_A_kernel(const int* __restrict__ ei, float* __restrict__ A) {
    __shared__ int   deg[32];
    __shared__ float dinv[32];
    __shared__ float cnt[1024];
    int g = blockIdx.x, t = threadIdx.x;
    if (t < 32) deg[t] = 1;
    for (int i = t; i < 1024; i += 128) cnt[i] = 0.f;
    __syncthreads();
    int src = ei[g * EPG + t] & 31;
    int dst = ei[NE + g * EPG + t] & 31;
    atomicAdd(&deg[src], 1);
    __syncthreads();
    if (t < 32) dinv[t] = rsqrtf((float)deg[t]);
    atomicAdd(&cnt[src * 32 + dst], 1.f);
    __syncthreads();
    for (int i = t; i < 1024; i += 128) {
        int r = i >> 5, c = i & 31;
        float v = cnt[i] + (r == c ? 1.f : 0.f);
        A[g * 1024 + i] = v * dinv[r] * dinv[c];
    }
}

// ================= fp16x3 GEMM: C = act(X @ W + bias) =================
// block tile 128x64, 8 warps (wm = w&3 over M, wn = w>>2 over N), warp tile 32x32.
// K chunked by 32 (2 x m16n8k16 steps), 3-pass hi/lo compensation.
// POOL=1: instead of storing C rows, emit per-graph (32-row) column max into
//         C[graph][col]  (graph = row/32; requires N % 128 == 0).
template <int ACT, int POOL>
__global__ void __launch_bounds__(256)
gemm_fp16_kernel(const float* __restrict__ X, const float* __restrict__ W,
                 const float* __restrict__ bias, float* __restrict__ C,
                 int N, int K, int M, const float* __restrict__ pa) {
    __shared__ uint32_t Ah[128 * GS], Al[128 * GS];
    __shared__ uint32_t Bh[64 * GS],  Bl[64 * GS];
    int tid = threadIdx.x, lane = tid & 31, w = tid >> 5;
    int wm = w & 3, wn = w >> 2;
    int gid = lane >> 2, tig = lane & 3;
    int R0 = blockIdx.y * 128, C0 = blockIdx.x * 64;
    float acc[2][4][4] = {};

    for (int k0 = 0; k0 < K; k0 += 32) {
#pragma unroll
        for (int it = 0; it < 8; it++) {           // stage A: 128 rows x 16 k-pairs
            int i = tid + it * 256;
            int row = i >> 4, kp = i & 15;
            int k = k0 + 2 * kp;
            const float* xr = X + (size_t)(R0 + row) * K;
            float v0 = (k < K)     ? xr[k]     : 0.f;
            float v1 = (k + 1 < K) ? xr[k + 1] : 0.f;
            uint32_t lo, hi = pack_hl(v0, v1, lo);
            Ah[row * GS + kp] = hi;
            Al[row * GS + kp] = lo;
        }
#pragma unroll
        for (int it = 0; it < 4; it++) {           // stage B: 64 cols x 16 k-pairs
            int i = tid + it * 256;
            int col = i & 63, kp = i >> 6;
            int k = k0 + 2 * kp, c = C0 + col;
            float v0 = 0.f, v1 = 0.f;
            if (c < M) {
                if (k < K)     v0 = W[(size_t)k * M + c];
                if (k + 1 < K) v1 = W[(size_t)(k + 1) * M + c];
            }
            uint32_t lo, hi = pack_hl(v0, v1, lo);
            Bh[col * GS + kp] = hi;
            Bl[col * GS + kp] = lo;
        }
        __syncthreads();
#pragma unroll
        for (int s = 0; s < 2; s++) {
            uint32_t ah[2][4], al[2][4], bh[4][2], bl[4][2];
            int p = s * 8 + tig;
#pragma unroll
            for (int mt = 0; mt < 2; mt++) {
                int r = wm * 32 + mt * 16 + gid;
                ah[mt][0] = Ah[r * GS + p];           al[mt][0] = Al[r * GS + p];
                ah[mt][1] = Ah[(r + 8) * GS + p];     al[mt][1] = Al[(r + 8) * GS + p];
                ah[mt][2] = Ah[r * GS + p + 4];       al[mt][2] = Al[r * GS + p + 4];
                ah[mt][3] = Ah[(r + 8) * GS + p + 4]; al[mt][3] = Al[(r + 8) * GS + p + 4];
            }
#pragma unroll
            for (int nt = 0; nt < 4; nt++) {
                int c = wn * 32 + nt * 8 + gid;
                bh[nt][0] = Bh[c * GS + p];      bl[nt][0] = Bl[c * GS + p];
                bh[nt][1] = Bh[c * GS + p + 4];  bl[nt][1] = Bl[c * GS + p + 4];
            }
#pragma unroll
            for (int mt = 0; mt < 2; mt++)
#pragma unroll
                for (int nt = 0; nt < 4; nt++) {
                    mma16(acc[mt][nt], ah[mt], bh[nt]);
                    mma16(acc[mt][nt], al[mt], bh[nt]);
                    mma16(acc[mt][nt], ah[mt], bl[nt]);
                }
        }
        __syncthreads();
    }

    float alpha = (ACT == 2) ? *pa : 0.f;
    if (POOL) {
        // relu(v+bias) then max over the warp's 32 rows (= one graph)
        float mx[4][2];
#pragma unroll
        for (int nt = 0; nt < 4; nt++) { mx[nt][0] = -3.4e38f; mx[nt][1] = -3.4e38f; }
#pragma unroll
        for (int nt = 0; nt < 4; nt++) {
#pragma unroll
            for (int q1 = 0; q1 < 2; q1++) {
                int col = C0 + wn * 32 + nt * 8 + 2 * tig + q1;
                float b = (col < M) ? bias[col] : 0.f;
#pragma unroll
                for (int mt = 0; mt < 2; mt++)
#pragma unroll
                    for (int qh = 0; qh < 2; qh++) {
                        float v = fmaxf(acc[mt][nt][qh * 2 + q1] + b, 0.f);
                        mx[nt][q1] = fmaxf(mx[nt][q1], v);
                    }
            }
        }
#pragma unroll
        for (int o = 4; o < 32; o <<= 1)
#pragma unroll
            for (int nt = 0; nt < 4; nt++) {
                mx[nt][0] = fmaxf(mx[nt][0], __shfl_xor_sync(0xffffffffu, mx[nt][0], o));
                mx[nt][1] = fmaxf(mx[nt][1], __shfl_xor_sync(0xffffffffu, mx[nt][1], o));
            }
        if (gid == 0) {
            int graph = (R0 >> 5) + wm;
#pragma unroll
            for (int nt = 0; nt < 4; nt++)
#pragma unroll
                for (int q1 = 0; q1 < 2; q1++) {
                    int col = C0 + wn * 32 + nt * 8 + 2 * tig + q1;
                    if (col < M) C[(size_t)graph * M + col] = mx[nt][q1];
                }
        }
    } else {
#pragma unroll
        for (int mt = 0; mt < 2; mt++)
#pragma unroll
            for (int nt = 0; nt < 4; nt++) {
                int row = R0 + wm * 32 + mt * 16 + gid;
                int col = C0 + wn * 32 + nt * 8 + 2 * tig;
#pragma unroll
                for (int q = 0; q < 4; q++) {
                    int r = row + (q >> 1) * 8;
                    int c = col + (q & 1);
                    if (c < M) {
                        float v = acc[mt][nt][q] + (bias ? bias[c] : 0.f);
                        if (ACT == 1) v = fmaxf(v, 0.f);
                        if (ACT == 2) v = (v >= 0.f) ? v : alpha * v;
                        C[(size_t)r * M + c] = v;
                    }
                }
            }
    }
}

// ================= propagation fp16x3: P_g = A_g (32x32) @ X_g (32xK) =================
// 1 block per graph, 4 warps, each warp owns a 16-col slice of a 64-col chunk.
// A fragments are K-invariant: preloaded once into registers.
__global__ void __launch_bounds__(128)
prop_fp16_kernel(const float* __restrict__ A, const float* __restrict__ X,
                 float* __restrict__ P, int K) {
    __shared__ uint32_t sAh[32 * GS], sAl[32 * GS];
    __shared__ uint32_t sXh[64 * GS], sXl[64 * GS];
    int g = blockIdx.x, tid = threadIdx.x, lane = tid & 31, w = tid >> 5;
    int gid = lane >> 2, tig = lane & 3;
    const float* Ag = A + g * 1024;
#pragma unroll
    for (int it = 0; it < 4; it++) {               // stage A: 32 rows x 16 pairs
        int i = tid + it * 128;
        int r = i >> 4, kp = i & 15;
        uint32_t lo, hi = pack_hl(Ag[r * 32 + 2 * kp], Ag[r * 32 + 2 * kp + 1], lo);
        sAh[r * GS + kp] = hi;
        sAl[r * GS + kp] = lo;
    }
    __syncthreads();
    uint32_t ah[2][2][4], al[2][2][4];             // [s][mt][4]
#pragma unroll
    for (int s = 0; s < 2; s++)
#pragma unroll
        for (int mt = 0; mt < 2; mt++) {
            int r = mt * 16 + gid;
            int p = s * 8 + tig;
            ah[s][mt][0] = sAh[r * GS + p];           al[s][mt][0] = sAl[r * GS + p];
            ah[s][mt][1] = sAh[(r + 8) * GS + p];     al[s][mt][1] = sAl[(r + 8) * GS + p];
            ah[s][mt][2] = sAh[r * GS + p + 4];       al[s][mt][2] = sAl[r * GS + p + 4];
            ah[s][mt][3] = sAh[(r + 8) * GS + p + 4]; al[s][mt][3] = sAl[(r + 8) * GS + p + 4];
        }
    const float* Xg = X + (size_t)g * 32 * K;
    float* Pg = P + (size_t)g * 32 * K;
    for (int f0 = 0; f0 < K; f0 += 64) {
        if (f0) __syncthreads();
#pragma unroll
        for (int it = 0; it < 8; it++) {           // stage X chunk: 64 feats x 16 node-pairs
            int i = tid + it * 128;
            int f = i & 63, kp = i >> 6;
            int ff = f0 + f;
            float v0 = 0.f, v1 = 0.f;
            if (ff < K) {
                v0 = Xg[(size_t)(2 * kp) * K + ff];
                v1 = Xg[(size_t)(2 * kp + 1) * K + ff];
            }
            uint32_t lo, hi = pack_hl(v0, v1, lo);
            sXh[f * GS + kp] = hi;
            sXl[f * GS + kp] = lo;
        }
        __syncthreads();
        float acc[2][2][4] = {};
#pragma unroll
        for (int s = 0; s < 2; s++) {
            uint32_t bh[2][2], bl[2][2];
            int p = s * 8 + tig;
#pragma unroll
            for (int nt = 0; nt < 2; nt++) {
                int c = w * 16 + nt * 8 + gid;
                bh[nt][0] = sXh[c * GS + p];      bl[nt][0] = sXl[c * GS + p];
                bh[nt][1] = sXh[c * GS + p + 4];  bl[nt][1] = sXl[c * GS + p + 4];
            }
#pragma unroll
            for (int mt = 0; mt < 2; mt++)
#pragma unroll
                for (int nt = 0; nt < 2; nt++) {
                    mma16(acc[mt][nt], ah[s][mt], bh[nt]);
                    mma16(acc[mt][nt], al[s][mt], bh[nt]);
                    mma16(acc[mt][nt], ah[s][mt], bl[nt]);
                }
        }
#pragma unroll
        for (int mt = 0; mt < 2; mt++)
#pragma unroll
            for (int nt = 0; nt < 2; nt++) {
                int row = mt * 16 + gid;
                int f = f0 + w * 16 + nt * 8 + 2 * tig;
#pragma unroll
                for (int q = 0; q < 4; q++) {
                    int r = row + (q >> 1) * 8;
                    int c = f + (q & 1);
                    if (c < K) Pg[(size_t)r * K + c] = acc[mt][nt][q];
                }
            }
    }
}

// ---------------- concat [g1,g2,c] + L2 normalize row ----------------
__global__ void catnorm_kernel(const float* __restrict__ g1, const float* __restrict__ g2,
                               const float* __restrict__ c, float* __restrict__ xc) {
    int g = blockIdx.x, t = threadIdx.x;
    float v0 = g1[g * 128 + t], v1 = g2[g * 128 + t], v2 = c[g * 128 + t];
    float ps = v0 * v0 + v1 * v1 + v2 * v2;
    __shared__ float red[4];
#pragma unroll
    for (int o = 16; o; o >>= 1) ps += __shfl_xor_sync(0xffffffffu, ps, o);
    if ((t & 31) == 0) red[t >> 5] = ps;
    __syncthreads();
    float tot = red[0] + red[1] + red[2] + red[3];
    float inv = 1.f / fmaxf(sqrtf(tot), 1e-12f);
    xc[g * 384 + t]       = v0 * inv;
    xc[g * 384 + 128 + t] = v1 * inv;
    xc[g * 384 + 256 + t] = v2 * inv;
}

// ---------------- final: sigmoid(x @ Wo + bo) ----------------
__global__ void final_kernel(const float* __restrict__ x, const float* __restrict__ Wo,
                             const float* __restrict__ bo, float* __restrict__ out) {
    int w = (blockIdx.x * blockDim.x + threadIdx.x) >> 5;
    int lane = threadIdx.x & 31;
    if (w >= NG) return;
    float acc = 0.f;
#pragma unroll
    for (int k = lane; k < 128; k += 32) acc = fmaf(x[w * 128 + k], Wo[k], acc);
#pragma unroll
    for (int o = 16; o; o >>= 1) acc += __shfl_xor_sync(0xffffffffu, acc, o);
    if (lane == 0) out[w] = 1.f / (1.f + expf(-(acc + bo[0])));
}

// ---------------- host side ----------------
static void gemm_launch(const float* X, const float* W, const float* bias, float* C,
                        int N, int K, int M, int act, int pool, const float* pa) {
    dim3 grid((M + 63) / 64, N / 128);
    if (pool)               gemm_fp16_kernel<1, 1><<<grid, 256>>>(X, W, bias, C, N, K, M, nullptr);
    else if (act == 0)      gemm_fp16_kernel<0, 0><<<grid, 256>>>(X, W, bias, C, N, K, M, nullptr);
    else if (act == 1)      gemm_fp16_kernel<1, 0><<<grid, 256>>>(X, W, bias, C, N, K, M, nullptr);
    else                    gemm_fp16_kernel<2, 0><<<grid, 256>>>(X, W, bias, C, N, K, M, pa);
}

extern "C" void kernel_launch(void* const* d_in, const int* in_sizes, int n_in,
                              void* d_out, int out_size) {
    const float* x1   = (const float*)d_in[0];
    const int*   ei1  = (const int*)d_in[1];
    const float* x2   = (const float*)d_in[2];
    const int*   ei2  = (const int*)d_in[3];
    const float* cell = (const float*)d_in[4];
    const float* W1  = (const float*)d_in[7],  *b1  = (const float*)d_in[8];
    const float* W2  = (const float*)d_in[9],  *b2  = (const float*)d_in[10];
    const float* W3  = (const float*)d_in[11], *b3  = (const float*)d_in[12];
    const float* Wg1 = (const float*)d_in[13], *bg1 = (const float*)d_in[14];
    const float* Wg2 = (const float*)d_in[15], *bg2 = (const float*)d_in[16];
    const float* Wr1 = (const float*)d_in[17], *br1 = (const float*)d_in[18];
    const float* Wr2 = (const float*)d_in[19], *br2 = (const float*)d_in[20];
    const float* Wr3 = (const float*)d_in[21], *br3 = (const float*)d_in[22];
    const float* Wf1 = (const float*)d_in[23], *bf1 = (const float*)d_in[24];
    const float* Wf2 = (const float*)d_in[25], *bf2 = (const float*)d_in[26];
    const float* Wo  = (const float*)d_in[27], *bo  = (const float*)d_in[28];
    const float* pa  = (const float*)d_in[29];
    float* out = (float*)d_out;

    float *A, *bufA, *bufB, *pool, *t512, *t256, *G1, *G2, *Cl, *XC;
    cudaGetSymbolAddress((void**)&A,    g_A);
    cudaGetSymbolAddress((void**)&bufA, g_bufA);
    cudaGetSymbolAddress((void**)&bufB, g_bufB);
    cudaGetSymbolAddress((void**)&pool, g_pool);
    cudaGetSymbolAddress((void**)&t512, g_t512);
    cudaGetSymbolAddress((void**)&t256, g_t256);
    cudaGetSymbolAddress((void**)&G1,   g_g1);
    cudaGetSymbolAddress((void**)&G2,   g_g2);
    cudaGetSymbolAddress((void**)&Cl,   g_cell);
    cudaGetSymbolAddress((void**)&XC,   g_xc);

    for (int d = 0; d < 2; d++) {
        const float* x  = d ? x2 : x1;
        const int*   ei = d ? ei2 : ei1;
        float*       G  = d ? G2 : G1;
        build_A_kernel<<<NG, 128>>>(ei, A);
        // GCN reordered: H = relu((A @ X) @ W + b)
        prop_fp16_kernel<<<NG, 128>>>(A, x, bufA, 78);
        gemm_launch(bufA, W1, b1, bufB, NN, 78, 78, 1, 0, pa);
        prop_fp16_kernel<<<NG, 128>>>(A, bufB, bufA, 78);
        gemm_launch(bufA, W2, b2, bufB, NN, 78, 156, 1, 0, pa);
        prop_fp16_kernel<<<NG, 128>>>(A, bufB, bufA, 156);
        // layer 3 GEMM with fused relu + per-graph max pool -> pool[NG x 312]
        gemm_launch(bufA, W3, b3, pool, NN, 156, 312, 1, 1, pa);
        gemm_launch(pool, Wg1, bg1, t512, NG, 312, 156, 1, 0, pa);
        gemm_launch(t512, Wg2, bg2, G,    NG, 156, 128, 0, 0, pa);
    }

    // cell-line MLP
    gemm_launch(cell, Wr1, br1, t512, NG, 1000, 512, 1, 0, pa);
    gemm_launch(t512, Wr2, br2, t256, NG, 512,  256, 1, 0, pa);
    gemm_launch(t256, Wr3, br3, Cl,   NG, 256,  128, 0, 0, pa);

    // concat + L2 normalize + fused head
    catnorm_kernel<<<NG, 128>>>(G1, G2, Cl, XC);
    gemm_launch(XC,   Wf1, bf1, t512, NG, 384, 512, 2, 0, pa);
    gemm_launch(t512, Wf2, bf2, t256, NG, 512, 128, 2, 0, pa);
    final_kernel<<<NG / 8, 256>>>(t256, Wo, bo, out);
}

// round 13
// speedup vs baseline: 2.0538x; 1.0327x over previous
#include <cuda_runtime.h>
#include <cuda_fp16.h>
#include <math.h>
#include <stdint.h>

#define NN 262144
#define NE 1048576
#define NG 8192
#define EPG 128
#define GS 20   // prop smem stride (uint32)
#define ST 20   // gemm smem stride (uint2); 20 % 16 == 4 -> conflict-free LDS.64 half-warps

// ---------------- scratch (sanctioned __device__ globals) ----------------
__device__ float g_A[NG * 1024];
__device__ float g_bufA[(size_t)NN * 312];     // used as uint2[NN*156] packed
__device__ float g_bufB[(size_t)NN * 312];     // float intermediate
__device__ float g_pool[NG * 312];             // used as uint2[NG*156]
__device__ float g_t512[NG * 512];             // used as uint2[NG*256]
__device__ float g_t256[NG * 256];             // used as uint2[NG*128] or float
__device__ float g_g1[NG * 128];
__device__ float g_g2[NG * 128];
__device__ float g_cell[NG * 128];
__device__ float g_xc[NG * 384];               // used as uint2[NG*192]
__device__ uint2 g_cellp[(size_t)NG * 500];
__device__ uint2 g_wp[536774];

// weight-pack offsets in g_wp (pairs x M)
#define O_W1  0
#define O_W2  3042
#define O_W3  9126
#define O_Wg1 33462
#define O_Wg2 57798
#define O_Wr1 67782
#define O_Wr2 323782
#define O_Wr3 389318
#define O_Wf1 405702
#define O_Wf2 504006

// ---------------- fp16 split helpers ----------------
__device__ __forceinline__ uint32_t pack_hl(float v0, float v1, uint32_t& lo) {
    __half h0 = __float2half_rn(v0), h1 = __float2half_rn(v1);
    __half l0 = __float2half_rn(v0 - __half2float(h0));
    __half l1 = __float2half_rn(v1 - __half2float(h1));
    lo = ((uint32_t)__half_as_ushort(l1) << 16) | __half_as_ushort(l0);
    return ((uint32_t)__half_as_ushort(h1) << 16) | __half_as_ushort(h0);
}

__device__ __forceinline__ void mma16(float* c, const uint32_t* a, const uint32_t* b) {
    asm volatile(
        "mma.sync.aligned.m16n8k16.row.col.f32.f16.f16.f32 "
        "{%0,%1,%2,%3}, {%4,%5,%6,%7}, {%8,%9}, {%0,%1,%2,%3};"
        : "+f"(c[0]), "+f"(c[1]), "+f"(c[2]), "+f"(c[3])
        : "r"(a[0]), "r"(a[1]), "r"(a[2]), "r"(a[3]), "r"(b[0]), "r"(b[1]));
}

// ---------------- pre-pack kernels ----------------
// W[K,M] row-major -> Wp[kp*M + c] = packed (W[2kp][c], W[2kp+1][c])
__global__ void packW_kernel(const float* __restrict__ W, uint2* __restrict__ out,
                             int K, int M) {
    int idx = blockIdx.x * blockDim.x + threadIdx.x;
    int Kp = K >> 1;
    if (idx >= Kp * M) return;
    int kp = idx / M, c = idx - kp * M;
    float v0 = W[(size_t)(2 * kp) * M + c];
    float v1 = W[(size_t)(2 * kp + 1) * M + c];
    uint32_t lo, hi = pack_hl(v0, v1, lo);
    out[idx] = make_uint2(hi, lo);
}
// X[N,K] row-major -> Xp[row*Kp + p] = packed (X[row][2p], X[row][2p+1])
__global__ void packX_kernel(const float* __restrict__ X, uint2* __restrict__ out,
                             int N, int K) {
    int Kp = K >> 1;
    int idx = blockIdx.x * blockDim.x + threadIdx.x;
    if (idx >= N * Kp) return;
    int row = idx / Kp, p = idx - row * Kp;
    float v0 = X[(size_t)row * K + 2 * p];
    float v1 = X[(size_t)row * K + 2 * p + 1];
    uint32_t lo, hi = pack_hl(v0, v1, lo);
    out[idx] = make_uint2(hi, lo);
}

// ---------------- build per-graph normalized adjacency ----------------
__global__ void build_A_kernel(const int* __restrict__ ei, float* __restrict__ A) {
    __shared__ int   deg[32];
    __shared__ float dinv[32];
    __shared__ float cnt[1024];
    int g = blockIdx.x, t = threadIdx.x;
    if (t < 32) deg[t] = 1;
    for (int i = t; i < 1024; i += 128) cnt[i] = 0.f;
    __syncthreads();
    int src = ei[g * EPG + t] & 31;
    int dst = ei[NE + g * EPG + t] & 31;
    atomicAdd(&deg[src], 1);
    __syncthreads();
    if (t < 32) dinv[t] = rsqrtf((float)deg[t]);
    atomicAdd(&cnt[src * 32 + dst], 1.f);
    __syncthreads();
    for (int i = t; i < 1024; i += 128) {
        int r = i >> 5, c = i & 31;
        float v = cnt[i] + (r == c ? 1.f : 0.f);
        A[g * 1024 + i] = v * dinv[r] * dinv[c];
    }
}

// ================= fp16x3 GEMM on pre-packed inputs =================
// Xp: [N, Kp] uint2 (hi,lo of k-pair); Wp: [Kp, M] uint2.
// block tile 128x128, 512 threads / 16 warps (4x4), warp tile 32x32.
// cp.async double-buffered K-chunks of 16 pairs (32 k).
// POOL=1: relu+bias then per-graph (32-row) max -> packed pairs at C[graph][c/2].
// OPACK=1: write packed uint2 col-pairs; else float.
#define ABUF (128 * ST)
#define GEMM_SMEM (4 * ABUF * 8)

template <int ACT, int OPACK, int POOL>
__global__ void __launch_bounds__(512)
gemm_fp16_kernel(const uint2* __restrict__ Xp, const uint2* __restrict__ Wp,
                 const float* __restrict__ bias, void* __restrict__ Cv,
                 int N, int Kp, int M, const float* __restrict__ pa) {
    extern __shared__ uint2 sm[];
    int tid = threadIdx.x, lane = tid & 31, w = tid >> 5;
    int wm = w & 3, wn = w >> 2;
    int gid = lane >> 2, tig = lane & 3;
    int R0 = blockIdx.y * 128, C0 = blockIdx.x * 128;
    float acc[2][4][4] = {};
    int NC = (Kp + 15) >> 4;

    auto stage = [&](int chunk, int buf) {
        int kp0 = chunk * 16;
        uint2* Ad = sm + buf * ABUF;
        uint2* Bd = sm + 2 * ABUF + buf * ABUF;
#pragma unroll
        for (int it = 0; it < 4; it++) {
            int i = tid + it * 512;
            int row = i >> 4, kpl = i & 15;
            int kp = kp0 + kpl;
            const uint2* src = Xp + (size_t)(R0 + row) * Kp + (kp < Kp ? kp : 0);
            uint32_t ss = (kp < Kp) ? 8u : 0u;
            uint32_t dst = (uint32_t)__cvta_generic_to_shared(Ad + row * ST + kpl);
            asm volatile("cp.async.ca.shared.global [%0], [%1], 8, %2;"
                         :: "r"(dst), "l"(src), "r"(ss));
        }
#pragma unroll
        for (int it = 0; it < 4; it++) {
            int i = tid + it * 512;
            int col = i & 127, kpl = i >> 7;
            int kp = kp0 + kpl, c = C0 + col;
            bool ok = (kp < Kp) && (c < M);
            const uint2* src = Wp + (ok ? ((size_t)kp * M + c) : 0);
            uint32_t ss = ok ? 8u : 0u;
            uint32_t dst = (uint32_t)__cvta_generic_to_shared(Bd + col * ST + kpl);
            asm volatile("cp.async.ca.shared.global [%0], [%1], 8, %2;"
                         :: "r"(dst), "l"(src), "r"(ss));
        }
        asm volatile("cp.async.commit_group;");
    };

    stage(0, 0);
    for (int ch = 0; ch < NC; ch++) {
        int buf = ch & 1;
        if (ch + 1 < NC) {
            stage(ch + 1, buf ^ 1);
            asm volatile("cp.async.wait_group 1;");
        } else {
            asm volatile("cp.async.wait_group 0;");
        }
        __syncthreads();
        const uint2* Ab = sm + buf * ABUF;
        const uint2* Bb = sm + 2 * ABUF + buf * ABUF;
#pragma unroll
        for (int s = 0; s < 2; s++) {
            int p = s * 8 + tig;
            uint32_t ah[2][4], al[2][4], bh[4][2], bl[4][2];
#pragma unroll
            for (int mt = 0; mt < 2; mt++) {
                int r = wm * 32 + mt * 16 + gid;
                uint2 v0 = Ab[r * ST + p];
                uint2 v1 = Ab[(r + 8) * ST + p];
                uint2 v2 = Ab[r * ST + p + 4];
                uint2 v3 = Ab[(r + 8) * ST + p + 4];
                ah[mt][0] = v0.x; al[mt][0] = v0.y;
                ah[mt][1] = v1.x; al[mt][1] = v1.y;
                ah[mt][2] = v2.x; al[mt][2] = v2.y;
                ah[mt][3] = v3.x; al[mt][3] = v3.y;
            }
#pragma unroll
            for (int nt = 0; nt < 4; nt++) {
                int c = wn * 32 + nt * 8 + gid;
                uint2 v0 = Bb[c * ST + p];
                uint2 v1 = Bb[c * ST + p + 4];
                bh[nt][0] = v0.x; bl[nt][0] = v0.y;
                bh[nt][1] = v1.x; bl[nt][1] = v1.y;
            }
#pragma unroll
            for (int mt = 0; mt < 2; mt++)
#pragma unroll
                for (int nt = 0; nt < 4; nt++) {
                    mma16(acc[mt][nt], ah[mt], bh[nt]);
                    mma16(acc[mt][nt], al[mt], bh[nt]);
                    mma16(acc[mt][nt], ah[mt], bl[nt]);
                }
        }
        __syncthreads();
    }

    float alpha = (ACT == 2) ? *pa : 0.f;
    if (POOL) {
        float mx[4][2];
#pragma unroll
        for (int nt = 0; nt < 4; nt++) { mx[nt][0] = -3.4e38f; mx[nt][1] = -3.4e38f; }
#pragma unroll
        for (int nt = 0; nt < 4; nt++)
#pragma unroll
            for (int q1 = 0; q1 < 2; q1++) {
                int col = C0 + wn * 32 + nt * 8 + 2 * tig + q1;
                float b = (col < M) ? bias[col] : 0.f;
#pragma unroll
                for (int mt = 0; mt < 2; mt++)
#pragma unroll
                    for (int qh = 0; qh < 2; qh++)
                        mx[nt][q1] = fmaxf(mx[nt][q1], fmaxf(acc[mt][nt][qh * 2 + q1] + b, 0.f));
            }
#pragma unroll
        for (int o = 4; o < 32; o <<= 1)
#pragma unroll
            for (int nt = 0; nt < 4; nt++) {
                mx[nt][0] = fmaxf(mx[nt][0], __shfl_xor_sync(0xffffffffu, mx[nt][0], o));
                mx[nt][1] = fmaxf(mx[nt][1], __shfl_xor_sync(0xffffffffu, mx[nt][1], o));
            }
        if (gid == 0) {
            int graph = (R0 >> 5) + wm;
            uint2* Cp = (uint2*)Cv;
#pragma unroll
            for (int nt = 0; nt < 4; nt++) {
                int c = C0 + wn * 32 + nt * 8 + 2 * tig;
                if (c < M) {
                    uint32_t lo, hi = pack_hl(mx[nt][0], mx[nt][1], lo);
                    Cp[(size_t)graph * (M >> 1) + (c >> 1)] = make_uint2(hi, lo);
                }
            }
        }
    } else if (OPACK) {
        uint2* Cp = (uint2*)Cv;
#pragma unroll
        for (int mt = 0; mt < 2; mt++)
#pragma unroll
            for (int nt = 0; nt < 4; nt++) {
                int row = R0 + wm * 32 + mt * 16 + gid;
                int c = C0 + wn * 32 + nt * 8 + 2 * tig;
                if (c < M) {
                    float b0 = bias[c], b1 = bias[c + 1];
                    float v0 = acc[mt][nt][0] + b0, v1 = acc[mt][nt][1] + b1;
                    float v2 = acc[mt][nt][2] + b0, v3 = acc[mt][nt][3] + b1;
                    if (ACT == 1) {
                        v0 = fmaxf(v0, 0.f); v1 = fmaxf(v1, 0.f);
                        v2 = fmaxf(v2, 0.f); v3 = fmaxf(v3, 0.f);
                    }
                    if (ACT == 2) {
                        v0 = (v0 >= 0.f) ? v0 : alpha * v0;
                        v1 = (v1 >= 0.f) ? v1 : alpha * v1;
                        v2 = (v2 >= 0.f) ? v2 : alpha * v2;
                        v3 = (v3 >= 0.f) ? v3 : alpha * v3;
                    }
                    uint32_t lo, hi = pack_hl(v0, v1, lo);
                    Cp[(size_t)row * (M >> 1) + (c >> 1)] = make_uint2(hi, lo);
                    hi = pack_hl(v2, v3, lo);
                    Cp[(size_t)(row + 8) * (M >> 1) + (c >> 1)] = make_uint2(hi, lo);
                }
            }
    } else {
        float* Cf = (float*)Cv;
#pragma unroll
        for (int mt = 0; mt < 2; mt++)
#pragma unroll
            for (int nt = 0; nt < 4; nt++) {
                int row = R0 + wm * 32 + mt * 16 + gid;
                int col = C0 + wn * 32 + nt * 8 + 2 * tig;
#pragma unroll
                for (int q = 0; q < 4; q++) {
                    int r = row + (q >> 1) * 8;
                    int c = col + (q & 1);
                    if (c < M) {
                        float v = acc[mt][nt][q] + (bias ? bias[c] : 0.f);
                        if (ACT == 1) v = fmaxf(v, 0.f);
                        if (ACT == 2) v = (v >= 0.f) ? v : alpha * v;
                        Cf[(size_t)r * M + c] = v;
                    }
                }
            }
    }
}

// ================= propagation fp16x3: packed output =================
// P_g = A_g (32x32) @ X_g (32xK); X float input; P packed uint2 (feature pairs).
__global__ void __launch_bounds__(128)
prop_fp16_kernel(const float* __restrict__ A, const float* __restrict__ X,
                 uint2* __restrict__ P, int K) {
    __shared__ uint32_t sAh[32 * GS], sAl[32 * GS];
    __shared__ uint32_t sXh[64 * GS], sXl[64 * GS];
    int g = blockIdx.x, tid = threadIdx.x, lane = tid & 31, w = tid >> 5;
    int gid = lane >> 2, tig = lane & 3;
    int Kp = K >> 1;
    const float* Ag = A + g * 1024;
#pragma unroll
    for (int it = 0; it < 4; it++) {
        int i = tid + it * 128;
        int r = i >> 4, kp = i & 15;
        uint32_t lo, hi = pack_hl(Ag[r * 32 + 2 * kp], Ag[r * 32 + 2 * kp + 1], lo);
        sAh[r * GS + kp] = hi;
        sAl[r * GS + kp] = lo;
    }
    __syncthreads();
    uint32_t ah[2][2][4], al[2][2][4];
#pragma unroll
    for (int s = 0; s < 2; s++)
#pragma unroll
        for (int mt = 0; mt < 2; mt++) {
            int r = mt * 16 + gid;
            int p = s * 8 + tig;
            ah[s][mt][0] = sAh[r * GS + p];           al[s][mt][0] = sAl[r * GS + p];
            ah[s][mt][1] = sAh[(r + 8) * GS + p];     al[s][mt][1] = sAl[(r + 8) * GS + p];
            ah[s][mt][2] = sAh[r * GS + p + 4];       al[s][mt][2] = sAl[r * GS + p + 4];
            ah[s][mt][3] = sAh[(r + 8) * GS + p + 4]; al[s][mt][3] = sAl[(r + 8) * GS + p + 4];
        }
    const float* Xg = X + (size_t)g * 32 * K;
    uint2* Pg = P + (size_t)g * 32 * Kp;
    for (int f0 = 0; f0 < K; f0 += 64) {
        if (f0) __syncthreads();
#pragma unroll
        for (int it = 0; it < 8; it++) {
            int i = tid + it * 128;
            int f = i & 63, kp = i >> 6;
            int ff = f0 + f;
            float v0 = 0.f, v1 = 0.f;
            if (ff < K) {
                v0 = Xg[(size_t)(2 * kp) * K + ff];
                v1 = Xg[(size_t)(2 * kp + 1) * K + ff];
            }
            uint32_t lo, hi = pack_hl(v0, v1, lo);
            sXh[f * GS + kp] = hi;
            sXl[f * GS + kp] = lo;
        }
        __syncthreads();
        float acc[2][2][4] = {};
#pragma unroll
        for (int s = 0; s < 2; s++) {
            uint32_t bh[2][2], bl[2][2];
            int p = s * 8 + tig;
#pragma unroll
            for (int nt = 0; nt < 2; nt++) {
                int c = w * 16 + nt * 8 + gid;
                bh[nt][0] = sXh[c * GS + p];      bl[nt][0] = sXl[c * GS + p];
                bh[nt][1] = sXh[c * GS + p + 4];  bl[nt][1] = sXl[c * GS + p + 4];
            }
#pragma unroll
            for (int mt = 0; mt < 2; mt++)
#pragma unroll
                for (int nt = 0; nt < 2; nt++) {
                    mma16(acc[mt][nt], ah[s][mt], bh[nt]);
                    mma16(acc[mt][nt], al[s][mt], bh[nt]);
                    mma16(acc[mt][nt], ah[s][mt], bl[nt]);
                }
        }
#pragma unroll
        for (int mt = 0; mt < 2; mt++)
#pragma unroll
            for (int nt = 0; nt < 2; nt++) {
                int row = mt * 16 + gid;
                int f = f0 + w * 16 + nt * 8 + 2 * tig;   // even
                if (f < K) {
                    uint32_t lo, hi = pack_hl(acc[mt][nt][0], acc[mt][nt][1], lo);
                    Pg[(size_t)row * Kp + (f >> 1)] = make_uint2(hi, lo);
                    hi = pack_hl(acc[mt][nt][2], acc[mt][nt][3], lo);
                    Pg[(size_t)(row + 8) * Kp + (f >> 1)] = make_uint2(hi, lo);
                }
            }
    }
}

// ---------------- concat [g1,g2,c] + L2 normalize -> packed pairs ----------------
__global__ void catnorm_kernel(const float* __restrict__ g1, const float* __restrict__ g2,
                               const float* __restrict__ c, uint2* __restrict__ xcp) {
    int g = blockIdx.x, t = threadIdx.x;   // 192 threads, pair (2t, 2t+1)
    const float* src = (t < 64) ? (g1 + g * 128) : (t < 128 ? (g2 + g * 128) : (c + g * 128));
    int off = (t & 63) * 2;
    float a0 = src[off], a1 = src[off + 1];
    float ps = a0 * a0 + a1 * a1;
    __shared__ float red[6];
#pragma unroll
    for (int o = 16; o; o >>= 1) ps += __shfl_xor_sync(0xffffffffu, ps, o);
    if ((t & 31) == 0) red[t >> 5] = ps;
    __syncthreads();
    float tot = red[0] + red[1] + red[2] + red[3] + red[4] + red[5];
    float inv = 1.f / fmaxf(sqrtf(tot), 1e-12f);
    uint32_t lo, hi = pack_hl(a0 * inv, a1 * inv, lo);
    xcp[g * 192 + t] = make_uint2(hi, lo);
}

// ---------------- final: sigmoid(x @ Wo + bo) ----------------
__global__ void final_kernel(const float* __restrict__ x, const float* __restrict__ Wo,
                             const float* __restrict__ bo, float* __restrict__ out) {
    int w = (blockIdx.x * blockDim.x + threadIdx.x) >> 5;
    int lane = threadIdx.x & 31;
    if (w >= NG) return;
    float acc = 0.f;
#pragma unroll
    for (int k = lane; k < 128; k += 32) acc = fmaf(x[w * 128 + k], Wo[k], acc);
#pragma unroll
    for (int o = 16; o; o >>= 1) acc += __shfl_xor_sync(0xffffffffu, acc, o);
    if (lane == 0) out[w] = 1.f / (1.f + expf(-(acc + bo[0])));
}

// ---------------- host side ----------------
static void gemm_launch(const uint2* Xp, const uint2* Wp, const float* bias, void* C,
                        int N, int Kp, int M, int act, int opack, int pool, const float* pa) {
    dim3 grid((M + 127) / 128, N / 128);
    if (pool)          gemm_fp16_kernel<1, 1, 1><<<grid, 512, GEMM_SMEM>>>(Xp, Wp, bias, C, N, Kp, M, nullptr);
    else if (act == 0) gemm_fp16_kernel<0, 0, 0><<<grid, 512, GEMM_SMEM>>>(Xp, Wp, bias, C, N, Kp, M, nullptr);
    else if (act == 1 && opack)  gemm_fp16_kernel<1, 1, 0><<<grid, 512, GEMM_SMEM>>>(Xp, Wp, bias, C, N, Kp, M, nullptr);
    else if (act == 1)           gemm_fp16_kernel<1, 0, 0><<<grid, 512, GEMM_SMEM>>>(Xp, Wp, bias, C, N, Kp, M, nullptr);
    else if (act == 2 && opack)  gemm_fp16_kernel<2, 1, 0><<<grid, 512, GEMM_SMEM>>>(Xp, Wp, bias, C, N, Kp, M, pa);
    else                         gemm_fp16_kernel<2, 0, 0><<<grid, 512, GEMM_SMEM>>>(Xp, Wp, bias, C, N, Kp, M, pa);
}

extern "C" void kernel_launch(void* const* d_in, const int* in_sizes, int n_in,
                              void* d_out, int out_size) {
    const float* x1   = (const float*)d_in[0];
    const int*   ei1  = (const int*)d_in[1];
    const float* x2   = (const float*)d_in[2];
    const int*   ei2  = (const int*)d_in[3];
    const float* cell = (const float*)d_in[4];
    const float* W1  = (const float*)d_in[7],  *b1  = (const float*)d_in[8];
    const float* W2  = (const float*)d_in[9],  *b2  = (const float*)d_in[10];
    const float* W3  = (const float*)d_in[11], *b3  = (const float*)d_in[12];
    const float* Wg1 = (const float*)d_in[13], *bg1 = (const float*)d_in[14];
    const float* Wg2 = (const float*)d_in[15], *bg2 = (const float*)d_in[16];
    const float* Wr1 = (const float*)d_in[17], *br1 = (const float*)d_in[18];
    const float* Wr2 = (const float*)d_in[19], *br2 = (const float*)d_in[20];
    const float* Wr3 = (const float*)d_in[21], *br3 = (const float*)d_in[22];
    const float* Wf1 = (const float*)d_in[23], *bf1 = (const float*)d_in[24];
    const float* Wf2 = (const float*)d_in[25], *bf2 = (const float*)d_in[26];
    const float* Wo  = (const float*)d_in[27], *bo  = (const float*)d_in[28];
    const float* pa  = (const float*)d_in[29];
    float* out = (float*)d_out;

    static int attr_done = 0;
    if (!attr_done) {
        cudaFuncSetAttribute(gemm_fp16_kernel<1,1,1>, cudaFuncAttributeMaxDynamicSharedMemorySize, GEMM_SMEM);
        cudaFuncSetAttribute(gemm_fp16_kernel<0,0,0>, cudaFuncAttributeMaxDynamicSharedMemorySize, GEMM_SMEM);
        cudaFuncSetAttribute(gemm_fp16_kernel<1,1,0>, cudaFuncAttributeMaxDynamicSharedMemorySize, GEMM_SMEM);
        cudaFuncSetAttribute(gemm_fp16_kernel<1,0,0>, cudaFuncAttributeMaxDynamicSharedMemorySize, GEMM_SMEM);
        cudaFuncSetAttribute(gemm_fp16_kernel<2,1,0>, cudaFuncAttributeMaxDynamicSharedMemorySize, GEMM_SMEM);
        cudaFuncSetAttribute(gemm_fp16_kernel<2,0,0>, cudaFuncAttributeMaxDynamicSharedMemorySize, GEMM_SMEM);
        attr_done = 1;
    }

    float *A, *bufA, *bufB, *pool, *t512, *t256, *G1, *G2, *Cl, *XC;
    uint2 *wp, *cellp;
    cudaGetSymbolAddress((void**)&A,    g_A);
    cudaGetSymbolAddress((void**)&bufA, g_bufA);
    cudaGetSymbolAddress((void**)&bufB, g_bufB);
    cudaGetSymbolAddress((void**)&pool, g_pool);
    cudaGetSymbolAddress((void**)&t512, g_t512);
    cudaGetSymbolAddress((void**)&t256, g_t256);
    cudaGetSymbolAddress((void**)&G1,   g_g1);
    cudaGetSymbolAddress((void**)&G2,   g_g2);
    cudaGetSymbolAddress((void**)&Cl,   g_cell);
    cudaGetSymbolAddress((void**)&XC,   g_xc);
    cudaGetSymbolAddress((void**)&wp,    g_wp);
    cudaGetSymbolAddress((void**)&cellp, g_cellp);
    uint2* bufAp = (uint2*)bufA;
    uint2* poolp = (uint2*)pool;
    uint2* t512p = (uint2*)t512;
    uint2* t256p = (uint2*)t256;
    uint2* XCp   = (uint2*)XC;

    // ---- pre-pack weights + cell (every call; cheap, deterministic) ----
    auto pw = [&](const float* W, int off, int K, int M) {
        int n = (K >> 1) * M;
        packW_kernel<<<(n + 255) / 256, 256>>>(W, wp + off, K, M);
    };
    pw(W1,  O_W1,  78,  78);
    pw(W2,  O_W2,  78,  156);
    pw(W3,  O_W3,  156, 312);
    pw(Wg1, O_Wg1, 312, 156);
    pw(Wg2, O_Wg2, 156, 128);
    pw(Wr1, O_Wr1, 1000, 512);
    pw(Wr2, O_Wr2, 512, 256);
    pw(Wr3, O_Wr3, 256, 128);
    pw(Wf1, O_Wf1, 384, 512);
    pw(Wf2, O_Wf2, 512, 128);
    packX_kernel<<<(NG * 500 + 255) / 256, 256>>>(cell, cellp, NG, 1000);

    for (int d = 0; d < 2; d++) {
        const float* x  = d ? x2 : x1;
        const int*   ei = d ? ei2 : ei1;
        float*       G  = d ? G2 : G1;
        build_A_kernel<<<NG, 128>>>(ei, A);
        // GCN reordered: H = relu((A @ X) @ W + b)
        prop_fp16_kernel<<<NG, 128>>>(A, x, bufAp, 78);
        gemm_launch(bufAp, wp + O_W1, b1, bufB, NN, 39, 78, 1, 0, 0, pa);
        prop_fp16_kernel<<<NG, 128>>>(A, bufB, bufAp, 78);
        gemm_launch(bufAp, wp + O_W2, b2, bufB, NN, 39, 156, 1, 0, 0, pa);
        prop_fp16_kernel<<<NG, 128>>>(A, bufB, bufAp, 156);
        // layer 3: fused relu + per-graph max pool -> packed pool[NG x 156 pairs]
        gemm_launch(bufAp, wp + O_W3, b3, poolp, NN, 78, 312, 1, 1, 1, pa);
        gemm_launch(poolp, wp + O_Wg1, bg1, t512p, NG, 156, 156, 1, 1, 0, pa);
        gemm_launch(t512p, wp + O_Wg2, bg2, G,    NG, 78, 128, 0, 0, 0, pa);
    }

    // cell-line MLP
    gemm_launch(cellp, wp + O_Wr1, br1, t512p, NG, 500, 512, 1, 1, 0, pa);
    gemm_launch(t512p, wp + O_Wr2, br2, t256p, NG, 256, 256, 1, 1, 0, pa);
    gemm_launch(t256p, wp + O_Wr3, br3, Cl,    NG, 128, 128, 0, 0, 0, pa);

    // concat + L2 normalize (packed) + fused head
    catnorm_kernel<<<NG, 192>>>(G1, G2, Cl, XCp);
    gemm_launch(XCp,   wp + O_Wf1, bf1, t512p, NG, 192, 512, 2, 1, 0, pa);
    gemm_launch(t512p, wp + O_Wf2, bf2, t256,  NG, 256, 128, 2, 0, 0, pa);
    final_kernel<<<NG / 8, 256>>>(t256, Wo, bo, out);
}

// round 14
// speedup vs baseline: 2.2798x; 1.1100x over previous
#include <cuda_runtime.h>
#include <cuda_fp16.h>
#include <math.h>
#include <stdint.h>

#define NN 262144
#define NE 1048576
#define NG 8192
#define EPG 128
#define GS 20   // prop smem stride (uint32)
#define ST 20   // gemm smem stride (uint2)

// ---------------- scratch (sanctioned __device__ globals) ----------------
__device__ float g_A[NG * 1024];
__device__ float g_bufA[(size_t)NN * 312];     // used as uint2[NN*156] packed
__device__ float g_bufB[(size_t)NN * 312];     // float intermediate
__device__ float g_pool[NG * 312];             // used as uint2[NG*156]
__device__ float g_t512[NG * 512];             // used as uint2[NG*256]
__device__ float g_t256[NG * 256];             // used as uint2[NG*128] or float
__device__ float g_g1[NG * 128];
__device__ float g_g2[NG * 128];
__device__ float g_cell[NG * 128];
__device__ float g_xc[NG * 384];               // used as uint2[NG*192]
__device__ uint2 g_cellp[(size_t)NG * 500];
__device__ uint2 g_wp[536774];

// weight-pack offsets in g_wp (pairs x M)
#define O_W1  0
#define O_W2  3042
#define O_W3  9126
#define O_Wg1 33462
#define O_Wg2 57798
#define O_Wr1 67782
#define O_Wr2 323782
#define O_Wr3 389318
#define O_Wf1 405702
#define O_Wf2 504006

// ---------------- fp16 split helpers ----------------
__device__ __forceinline__ uint32_t pack_hl(float v0, float v1, uint32_t& lo) {
    __half h0 = __float2half_rn(v0), h1 = __float2half_rn(v1);
    __half l0 = __float2half_rn(v0 - __half2float(h0));
    __half l1 = __float2half_rn(v1 - __half2float(h1));
    lo = ((uint32_t)__half_as_ushort(l1) << 16) | __half_as_ushort(l0);
    return ((uint32_t)__half_as_ushort(h1) << 16) | __half_as_ushort(h0);
}

__device__ __forceinline__ void mma16(float* c, const uint32_t* a, const uint32_t* b) {
    asm volatile(
        "mma.sync.aligned.m16n8k16.row.col.f32.f16.f16.f32 "
        "{%0,%1,%2,%3}, {%4,%5,%6,%7}, {%8,%9}, {%0,%1,%2,%3};"
        : "+f"(c[0]), "+f"(c[1]), "+f"(c[2]), "+f"(c[3])
        : "r"(a[0]), "r"(a[1]), "r"(a[2]), "r"(a[3]), "r"(b[0]), "r"(b[1]));
}

// ---------------- pre-pack kernels ----------------
__global__ void packW_kernel(const float* __restrict__ W, uint2* __restrict__ out,
                             int K, int M) {
    int idx = blockIdx.x * blockDim.x + threadIdx.x;
    int Kp = K >> 1;
    if (idx >= Kp * M) return;
    int kp = idx / M, c = idx - kp * M;
    float v0 = W[(size_t)(2 * kp) * M + c];
    float v1 = W[(size_t)(2 * kp + 1) * M + c];
    uint32_t lo, hi = pack_hl(v0, v1, lo);
    out[idx] = make_uint2(hi, lo);
}
__global__ void packX_kernel(const float* __restrict__ X, uint2* __restrict__ out,
                             int N, int K) {
    int Kp = K >> 1;
    int idx = blockIdx.x * blockDim.x + threadIdx.x;
    if (idx >= N * Kp) return;
    int row = idx / Kp, p = idx - row * Kp;
    float v0 = X[(size_t)row * K + 2 * p];
    float v1 = X[(size_t)row * K + 2 * p + 1];
    uint32_t lo, hi = pack_hl(v0, v1, lo);
    out[idx] = make_uint2(hi, lo);
}

// ---------------- build per-graph normalized adjacency ----------------
__global__ void build_A_kernel(const int* __restrict__ ei, float* __restrict__ A) {
    __shared__ int   deg[32];
    __shared__ float dinv[32];
    __shared__ float cnt[1024];
    int g = blockIdx.x, t = threadIdx.x;
    if (t < 32) deg[t] = 1;
    for (int i = t; i < 1024; i += 128) cnt[i] = 0.f;
    __syncthreads();
    int src = ei[g * EPG + t] & 31;
    int dst = ei[NE + g * EPG + t] & 31;
    atomicAdd(&deg[src], 1);
    __syncthreads();
    if (t < 32) dinv[t] = rsqrtf((float)deg[t]);
    atomicAdd(&cnt[src * 32 + dst], 1.f);
    __syncthreads();
    for (int i = t; i < 1024; i += 128) {
        int r = i >> 5, c = i & 31;
        float v = cnt[i] + (r == c ? 1.f : 0.f);
        A[g * 1024 + i] = v * dinv[r] * dinv[c];
    }
}

// ================= fp16 split GEMM on pre-packed inputs =================
// PASSES=3: hi*hi + lo*hi + hi*lo (fp32-class); PASSES=2: drop hi*lo (~3e-4 rel).
#define ABUF (128 * ST)
#define GEMM_SMEM (4 * ABUF * 8)

template <int ACT, int OPACK, int POOL, int PASSES>
__global__ void __launch_bounds__(512)
gemm_fp16_kernel(const uint2* __restrict__ Xp, const uint2* __restrict__ Wp,
                 const float* __restrict__ bias, void* __restrict__ Cv,
                 int N, int Kp, int M, const float* __restrict__ pa) {
    extern __shared__ uint2 sm[];
    int tid = threadIdx.x, lane = tid & 31, w = tid >> 5;
    int wm = w & 3, wn = w >> 2;
    int gid = lane >> 2, tig = lane & 3;
    int R0 = blockIdx.y * 128, C0 = blockIdx.x * 128;
    float acc[2][4][4] = {};
    int NC = (Kp + 15) >> 4;

    auto stage = [&](int chunk, int buf) {
        int kp0 = chunk * 16;
        uint2* Ad = sm + buf * ABUF;
        uint2* Bd = sm + 2 * ABUF + buf * ABUF;
#pragma unroll
        for (int it = 0; it < 4; it++) {
            int i = tid + it * 512;
            int row = i >> 4, kpl = i & 15;
            int kp = kp0 + kpl;
            const uint2* src = Xp + (size_t)(R0 + row) * Kp + (kp < Kp ? kp : 0);
            uint32_t ss = (kp < Kp) ? 8u : 0u;
            uint32_t dst = (uint32_t)__cvta_generic_to_shared(Ad + row * ST + kpl);
            asm volatile("cp.async.ca.shared.global [%0], [%1], 8, %2;"
                         :: "r"(dst), "l"(src), "r"(ss));
        }
#pragma unroll
        for (int it = 0; it < 4; it++) {
            int i = tid + it * 512;
            int col = i & 127, kpl = i >> 7;
            int kp = kp0 + kpl, c = C0 + col;
            bool ok = (kp < Kp) && (c < M);
            const uint2* src = Wp + (ok ? ((size_t)kp * M + c) : 0);
            uint32_t ss = ok ? 8u : 0u;
            uint32_t dst = (uint32_t)__cvta_generic_to_shared(Bd + col * ST + kpl);
            asm volatile("cp.async.ca.shared.global [%0], [%1], 8, %2;"
                         :: "r"(dst), "l"(src), "r"(ss));
        }
        asm volatile("cp.async.commit_group;");
    };

    stage(0, 0);
    for (int ch = 0; ch < NC; ch++) {
        int buf = ch & 1;
        if (ch + 1 < NC) {
            stage(ch + 1, buf ^ 1);
            asm volatile("cp.async.wait_group 1;");
        } else {
            asm volatile("cp.async.wait_group 0;");
        }
        __syncthreads();
        const uint2* Ab = sm + buf * ABUF;
        const uint2* Bb = sm + 2 * ABUF + buf * ABUF;
#pragma unroll
        for (int s = 0; s < 2; s++) {
            int p = s * 8 + tig;
            uint32_t ah[2][4], al[2][4], bh[4][2], bl[4][2];
#pragma unroll
            for (int mt = 0; mt < 2; mt++) {
                int r = wm * 32 + mt * 16 + gid;
                uint2 v0 = Ab[r * ST + p];
                uint2 v1 = Ab[(r + 8) * ST + p];
                uint2 v2 = Ab[r * ST + p + 4];
                uint2 v3 = Ab[(r + 8) * ST + p + 4];
                ah[mt][0] = v0.x; al[mt][0] = v0.y;
                ah[mt][1] = v1.x; al[mt][1] = v1.y;
                ah[mt][2] = v2.x; al[mt][2] = v2.y;
                ah[mt][3] = v3.x; al[mt][3] = v3.y;
            }
#pragma unroll
            for (int nt = 0; nt < 4; nt++) {
                int c = wn * 32 + nt * 8 + gid;
                uint2 v0 = Bb[c * ST + p];
                uint2 v1 = Bb[c * ST + p + 4];
                bh[nt][0] = v0.x; bl[nt][0] = v0.y;
                bh[nt][1] = v1.x; bl[nt][1] = v1.y;
            }
#pragma unroll
            for (int mt = 0; mt < 2; mt++)
#pragma unroll
                for (int nt = 0; nt < 4; nt++) {
                    mma16(acc[mt][nt], ah[mt], bh[nt]);
                    mma16(acc[mt][nt], al[mt], bh[nt]);
                    if (PASSES == 3) mma16(acc[mt][nt], ah[mt], bl[nt]);
                }
        }
        __syncthreads();
    }

    float alpha = (ACT == 2) ? *pa : 0.f;
    if (POOL) {
        float mx[4][2];
#pragma unroll
        for (int nt = 0; nt < 4; nt++) { mx[nt][0] = -3.4e38f; mx[nt][1] = -3.4e38f; }
#pragma unroll
        for (int nt = 0; nt < 4; nt++)
#pragma unroll
            for (int q1 = 0; q1 < 2; q1++) {
                int col = C0 + wn * 32 + nt * 8 + 2 * tig + q1;
                float b = (col < M) ? bias[col] : 0.f;
#pragma unroll
                for (int mt = 0; mt < 2; mt++)
#pragma unroll
                    for (int qh = 0; qh < 2; qh++)
                        mx[nt][q1] = fmaxf(mx[nt][q1], fmaxf(acc[mt][nt][qh * 2 + q1] + b, 0.f));
            }
#pragma unroll
        for (int o = 4; o < 32; o <<= 1)
#pragma unroll
            for (int nt = 0; nt < 4; nt++) {
                mx[nt][0] = fmaxf(mx[nt][0], __shfl_xor_sync(0xffffffffu, mx[nt][0], o));
                mx[nt][1] = fmaxf(mx[nt][1], __shfl_xor_sync(0xffffffffu, mx[nt][1], o));
            }
        if (gid == 0) {
            int graph = (R0 >> 5) + wm;
            uint2* Cp = (uint2*)Cv;
#pragma unroll
            for (int nt = 0; nt < 4; nt++) {
                int c = C0 + wn * 32 + nt * 8 + 2 * tig;
                if (c < M) {
                    uint32_t lo, hi = pack_hl(mx[nt][0], mx[nt][1], lo);
                    Cp[(size_t)graph * (M >> 1) + (c >> 1)] = make_uint2(hi, lo);
                }
            }
        }
    } else if (OPACK) {
        uint2* Cp = (uint2*)Cv;
#pragma unroll
        for (int mt = 0; mt < 2; mt++)
#pragma unroll
            for (int nt = 0; nt < 4; nt++) {
                int row = R0 + wm * 32 + mt * 16 + gid;
                int c = C0 + wn * 32 + nt * 8 + 2 * tig;
                if (c < M) {
                    float b0 = bias[c], b1 = bias[c + 1];
                    float v0 = acc[mt][nt][0] + b0, v1 = acc[mt][nt][1] + b1;
                    float v2 = acc[mt][nt][2] + b0, v3 = acc[mt][nt][3] + b1;
                    if (ACT == 1) {
                        v0 = fmaxf(v0, 0.f); v1 = fmaxf(v1, 0.f);
                        v2 = fmaxf(v2, 0.f); v3 = fmaxf(v3, 0.f);
                    }
                    if (ACT == 2) {
                        v0 = (v0 >= 0.f) ? v0 : alpha * v0;
                        v1 = (v1 >= 0.f) ? v1 : alpha * v1;
                        v2 = (v2 >= 0.f) ? v2 : alpha * v2;
                        v3 = (v3 >= 0.f) ? v3 : alpha * v3;
                    }
                    uint32_t lo, hi = pack_hl(v0, v1, lo);
                    Cp[(size_t)row * (M >> 1) + (c >> 1)] = make_uint2(hi, lo);
                    hi = pack_hl(v2, v3, lo);
                    Cp[(size_t)(row + 8) * (M >> 1) + (c >> 1)] = make_uint2(hi, lo);
                }
            }
    } else {
        float* Cf = (float*)Cv;
#pragma unroll
        for (int mt = 0; mt < 2; mt++)
#pragma unroll
            for (int nt = 0; nt < 4; nt++) {
                int row = R0 + wm * 32 + mt * 16 + gid;
                int col = C0 + wn * 32 + nt * 8 + 2 * tig;
#pragma unroll
                for (int q = 0; q < 4; q++) {
                    int r = row + (q >> 1) * 8;
                    int c = col + (q & 1);
                    if (c < M) {
                        float v = acc[mt][nt][q] + (bias ? bias[c] : 0.f);
                        if (ACT == 1) v = fmaxf(v, 0.f);
                        if (ACT == 2) v = (v >= 0.f) ? v : alpha * v;
                        Cf[(size_t)r * M + c] = v;
                    }
                }
            }
    }
}

// ================= propagation fp16x3: packed output =================
__global__ void __launch_bounds__(128)
prop_fp16_kernel(const float* __restrict__ A, const float* __restrict__ X,
                 uint2* __restrict__ P, int K) {
    __shared__ uint32_t sAh[32 * GS], sAl[32 * GS];
    __shared__ uint32_t sXh[64 * GS], sXl[64 * GS];
    int g = blockIdx.x, tid = threadIdx.x, lane = tid & 31, w = tid >> 5;
    int gid = lane >> 2, tig = lane & 3;
    int Kp = K >> 1;
    const float* Ag = A + g * 1024;
#pragma unroll
    for (int it = 0; it < 4; it++) {
        int i = tid + it * 128;
        int r = i >> 4, kp = i & 15;
        uint32_t lo, hi = pack_hl(Ag[r * 32 + 2 * kp], Ag[r * 32 + 2 * kp + 1], lo);
        sAh[r * GS + kp] = hi;
        sAl[r * GS + kp] = lo;
    }
    __syncthreads();
    uint32_t ah[2][2][4], al[2][2][4];
#pragma unroll
    for (int s = 0; s < 2; s++)
#pragma unroll
        for (int mt = 0; mt < 2; mt++) {
            int r = mt * 16 + gid;
            int p = s * 8 + tig;
            ah[s][mt][0] = sAh[r * GS + p];           al[s][mt][0] = sAl[r * GS + p];
            ah[s][mt][1] = sAh[(r + 8) * GS + p];     al[s][mt][1] = sAl[(r + 8) * GS + p];
            ah[s][mt][2] = sAh[r * GS + p + 4];       al[s][mt][2] = sAl[r * GS + p + 4];
            ah[s][mt][3] = sAh[(r + 8) * GS + p + 4]; al[s][mt][3] = sAl[(r + 8) * GS + p + 4];
        }
    const float* Xg = X + (size_t)g * 32 * K;
    uint2* Pg = P + (size_t)g * 32 * Kp;
    for (int f0 = 0; f0 < K; f0 += 64) {
        if (f0) __syncthreads();
#pragma unroll
        for (int it = 0; it < 8; it++) {
            int i = tid + it * 128;
            int f = i & 63, kp = i >> 6;
            int ff = f0 + f;
            float v0 = 0.f, v1 = 0.f;
            if (ff < K) {
                v0 = Xg[(size_t)(2 * kp) * K + ff];
                v1 = Xg[(size_t)(2 * kp + 1) * K + ff];
            }
            uint32_t lo, hi = pack_hl(v0, v1, lo);
            sXh[f * GS + kp] = hi;
            sXl[f * GS + kp] = lo;
        }
        __syncthreads();
        float acc[2][2][4] = {};
#pragma unroll
        for (int s = 0; s < 2; s++) {
            uint32_t bh[2][2], bl[2][2];
            int p = s * 8 + tig;
#pragma unroll
            for (int nt = 0; nt < 2; nt++) {
                int c = w * 16 + nt * 8 + gid;
                bh[nt][0] = sXh[c * GS + p];      bl[nt][0] = sXl[c * GS + p];
                bh[nt][1] = sXh[c * GS + p + 4];  bl[nt][1] = sXl[c * GS + p + 4];
            }
#pragma unroll
            for (int mt = 0; mt < 2; mt++)
#pragma unroll
                for (int nt = 0; nt < 2; nt++) {
                    mma16(acc[mt][nt], ah[s][mt], bh[nt]);
                    mma16(acc[mt][nt], al[s][mt], bh[nt]);
                    mma16(acc[mt][nt], ah[s][mt], bl[nt]);
                }
        }
#pragma unroll
        for (int mt = 0; mt < 2; mt++)
#pragma unroll
            for (int nt = 0; nt < 2; nt++) {
                int row = mt * 16 + gid;
                int f = f0 + w * 16 + nt * 8 + 2 * tig;
                if (f < K) {
                    uint32_t lo, hi = pack_hl(acc[mt][nt][0], acc[mt][nt][1], lo);
                    Pg[(size_t)row * Kp + (f >> 1)] = make_uint2(hi, lo);
                    hi = pack_hl(acc[mt][nt][2], acc[mt][nt][3], lo);
                    Pg[(size_t)(row + 8) * Kp + (f >> 1)] = make_uint2(hi, lo);
                }
            }
    }
}

// ---------------- concat [g1,g2,c] + L2 normalize -> packed pairs ----------------
__global__ void catnorm_kernel(const float* __restrict__ g1, const float* __restrict__ g2,
                               const float* __restrict__ c, uint2* __restrict__ xcp) {
    int g = blockIdx.x, t = threadIdx.x;
    const float* src = (t < 64) ? (g1 + g * 128) : (t < 128 ? (g2 + g * 128) : (c + g * 128));
    int off = (t & 63) * 2;
    float a0 = src[off], a1 = src[off + 1];
    float ps = a0 * a0 + a1 * a1;
    __shared__ float red[6];
#pragma unroll
    for (int o = 16; o; o >>= 1) ps += __shfl_xor_sync(0xffffffffu, ps, o);
    if ((t & 31) == 0) red[t >> 5] = ps;
    __syncthreads();
    float tot = red[0] + red[1] + red[2] + red[3] + red[4] + red[5];
    float inv = 1.f / fmaxf(sqrtf(tot), 1e-12f);
    uint32_t lo, hi = pack_hl(a0 * inv, a1 * inv, lo);
    xcp[g * 192 + t] = make_uint2(hi, lo);
}

// ---------------- final: sigmoid(x @ Wo + bo) ----------------
__global__ void final_kernel(const float* __restrict__ x, const float* __restrict__ Wo,
                             const float* __restrict__ bo, float* __restrict__ out) {
    int w = (blockIdx.x * blockDim.x + threadIdx.x) >> 5;
    int lane = threadIdx.x & 31;
    if (w >= NG) return;
    float acc = 0.f;
#pragma unroll
    for (int k = lane; k < 128; k += 32) acc = fmaf(x[w * 128 + k], Wo[k], acc);
#pragma unroll
    for (int o = 16; o; o >>= 1) acc += __shfl_xor_sync(0xffffffffu, acc, o);
    if (lane == 0) out[w] = 1.f / (1.f + expf(-(acc + bo[0])));
}

// ---------------- host side ----------------
static void gemm_launch(const uint2* Xp, const uint2* Wp, const float* bias, void* C,
                        int N, int Kp, int M, int act, int opack, int pool, int passes,
                        const float* pa) {
    dim3 grid((M + 127) / 128, N / 128);
    if (pool)
        gemm_fp16_kernel<1, 1, 1, 2><<<grid, 512, GEMM_SMEM>>>(Xp, Wp, bias, C, N, Kp, M, nullptr);
    else if (act == 1 && !opack)
        gemm_fp16_kernel<1, 0, 0, 2><<<grid, 512, GEMM_SMEM>>>(Xp, Wp, bias, C, N, Kp, M, nullptr);
    else if (act == 1 && opack && passes == 2)
        gemm_fp16_kernel<1, 1, 0, 2><<<grid, 512, GEMM_SMEM>>>(Xp, Wp, bias, C, N, Kp, M, nullptr);
    else if (act == 1 && opack)
        gemm_fp16_kernel<1, 1, 0, 3><<<grid, 512, GEMM_SMEM>>>(Xp, Wp, bias, C, N, Kp, M, nullptr);
    else if (act == 0)
        gemm_fp16_kernel<0, 0, 0, 3><<<grid, 512, GEMM_SMEM>>>(Xp, Wp, bias, C, N, Kp, M, nullptr);
    else if (act == 2 && opack)
        gemm_fp16_kernel<2, 1, 0, 3><<<grid, 512, GEMM_SMEM>>>(Xp, Wp, bias, C, N, Kp, M, pa);
    else
        gemm_fp16_kernel<2, 0, 0, 3><<<grid, 512, GEMM_SMEM>>>(Xp, Wp, bias, C, N, Kp, M, pa);
}

extern "C" void kernel_launch(void* const* d_in, const int* in_sizes, int n_in,
                              void* d_out, int out_size) {
    const float* x1   = (const float*)d_in[0];
    const int*   ei1  = (const int*)d_in[1];
    const float* x2   = (const float*)d_in[2];
    const int*   ei2  = (const int*)d_in[3];
    const float* cell = (const float*)d_in[4];
    const float* W1  = (const float*)d_in[7],  *b1  = (const float*)d_in[8];
    const float* W2  = (const float*)d_in[9],  *b2  = (const float*)d_in[10];
    const float* W3  = (const float*)d_in[11], *b3  = (const float*)d_in[12];
    const float* Wg1 = (const float*)d_in[13], *bg1 = (const float*)d_in[14];
    const float* Wg2 = (const float*)d_in[15], *bg2 = (const float*)d_in[16];
    const float* Wr1 = (const float*)d_in[17], *br1 = (const float*)d_in[18];
    const float* Wr2 = (const float*)d_in[19], *br2 = (const float*)d_in[20];
    const float* Wr3 = (const float*)d_in[21], *br3 = (const float*)d_in[22];
    const float* Wf1 = (const float*)d_in[23], *bf1 = (const float*)d_in[24];
    const float* Wf2 = (const float*)d_in[25], *bf2 = (const float*)d_in[26];
    const float* Wo  = (const float*)d_in[27], *bo  = (const float*)d_in[28];
    const float* pa  = (const float*)d_in[29];
    float* out = (float*)d_out;

    static int attr_done = 0;
    if (!attr_done) {
        cudaFuncSetAttribute(gemm_fp16_kernel<1,1,1,2>, cudaFuncAttributeMaxDynamicSharedMemorySize, GEMM_SMEM);
        cudaFuncSetAttribute(gemm_fp16_kernel<1,0,0,2>, cudaFuncAttributeMaxDynamicSharedMemorySize, GEMM_SMEM);
        cudaFuncSetAttribute(gemm_fp16_kernel<1,1,0,2>, cudaFuncAttributeMaxDynamicSharedMemorySize, GEMM_SMEM);
        cudaFuncSetAttribute(gemm_fp16_kernel<1,1,0,3>, cudaFuncAttributeMaxDynamicSharedMemorySize, GEMM_SMEM);
        cudaFuncSetAttribute(gemm_fp16_kernel<0,0,0,3>, cudaFuncAttributeMaxDynamicSharedMemorySize, GEMM_SMEM);
        cudaFuncSetAttribute(gemm_fp16_kernel<2,1,0,3>, cudaFuncAttributeMaxDynamicSharedMemorySize, GEMM_SMEM);
        cudaFuncSetAttribute(gemm_fp16_kernel<2,0,0,3>, cudaFuncAttributeMaxDynamicSharedMemorySize, GEMM_SMEM);
        attr_done = 1;
    }

    float *A, *bufA, *bufB, *pool, *t512, *t256, *G1, *G2, *Cl, *XC;
    uint2 *wp, *cellp;
    cudaGetSymbolAddress((void**)&A,    g_A);
    cudaGetSymbolAddress((void**)&bufA, g_bufA);
    cudaGetSymbolAddress((void**)&bufB, g_bufB);
    cudaGetSymbolAddress((void**)&pool, g_pool);
    cudaGetSymbolAddress((void**)&t512, g_t512);
    cudaGetSymbolAddress((void**)&t256, g_t256);
    cudaGetSymbolAddress((void**)&G1,   g_g1);
    cudaGetSymbolAddress((void**)&G2,   g_g2);
    cudaGetSymbolAddress((void**)&Cl,   g_cell);
    cudaGetSymbolAddress((void**)&XC,   g_xc);
    cudaGetSymbolAddress((void**)&wp,    g_wp);
    cudaGetSymbolAddress((void**)&cellp, g_cellp);
    uint2* bufAp = (uint2*)bufA;
    uint2* poolp = (uint2*)pool;
    uint2* t512p = (uint2*)t512;
    uint2* t256p = (uint2*)t256;
    uint2* XCp   = (uint2*)XC;

    // ---- pre-pack weights + cell ----
    auto pw = [&](const float* W, int off, int K, int M) {
        int n = (K >> 1) * M;
        packW_kernel<<<(n + 255) / 256, 256>>>(W, wp + off, K, M);
    };
    pw(W1,  O_W1,  78,  78);
    pw(W2,  O_W2,  78,  156);
    pw(W3,  O_W3,  156, 312);
    pw(Wg1, O_Wg1, 312, 156);
    pw(Wg2, O_Wg2, 156, 128);
    pw(Wr1, O_Wr1, 1000, 512);
    pw(Wr2, O_Wr2, 512, 256);
    pw(Wr3, O_Wr3, 256, 128);
    pw(Wf1, O_Wf1, 384, 512);
    pw(Wf2, O_Wf2, 512, 128);
    packX_kernel<<<(NG * 500 + 255) / 256, 256>>>(cell, cellp, NG, 1000);

    for (int d = 0; d < 2; d++) {
        const float* x  = d ? x2 : x1;
        const int*   ei = d ? ei2 : ei1;
        float*       G  = d ? G2 : G1;
        build_A_kernel<<<NG, 128>>>(ei, A);
        // GCN reordered: H = relu((A @ X) @ W + b)
        prop_fp16_kernel<<<NG, 128>>>(A, x, bufAp, 78);
        gemm_launch(bufAp, wp + O_W1, b1, bufB, NN, 39, 78, 1, 0, 0, 2, pa);
        prop_fp16_kernel<<<NG, 128>>>(A, bufB, bufAp, 78);
        gemm_launch(bufAp, wp + O_W2, b2, bufB, NN, 39, 156, 1, 0, 0, 2, pa);
        prop_fp16_kernel<<<NG, 128>>>(A, bufB, bufAp, 156);
        // layer 3: fused relu + per-graph max pool (2-pass)
        gemm_launch(bufAp, wp + O_W3, b3, poolp, NN, 78, 312, 1, 1, 1, 2, pa);
        gemm_launch(poolp, wp + O_Wg1, bg1, t512p, NG, 156, 156, 1, 1, 0, 3, pa);
        gemm_launch(t512p, wp + O_Wg2, bg2, G,    NG, 78, 128, 0, 0, 0, 3, pa);
    }

    // cell-line MLP (first two layers 2-pass)
    gemm_launch(cellp, wp + O_Wr1, br1, t512p, NG, 500, 512, 1, 1, 0, 2, pa);
    gemm_launch(t512p, wp + O_Wr2, br2, t256p, NG, 256, 256, 1, 1, 0, 2, pa);
    gemm_launch(t256p, wp + O_Wr3, br3, Cl,    NG, 128, 128, 0, 0, 0, 3, pa);

    // concat + L2 normalize (packed) + fused head
    catnorm_kernel<<<NG, 192>>>(G1, G2, Cl, XCp);
    gemm_launch(XCp,   wp + O_Wf1, bf1, t512p, NG, 192, 512, 2, 1, 0, 3, pa);
    gemm_launch(t512p, wp + O_Wf2, bf2, t256,  NG, 256, 128, 2, 0, 0, 3, pa);
    final_kernel<<<NG / 8, 256>>>(t256, Wo, bo, out);
}

// round 15
// speedup vs baseline: 4.9028x; 2.1505x over previous
#include <cuda_runtime.h>
#include <cuda_fp16.h>
#include <math.h>
#include <stdint.h>

#define NN 262144
#define NE 1048576
#define NG 8192
#define EPG 128
#define AST 20    // gemm A smem stride (words)
#define BST 136   // gemm B smem stride (words); 136 % 32 == 8 -> conflict-free
#define PST 20    // prop smem strides (words)

// ---------------- scratch (sanctioned __device__ globals) ----------------
__device__ float g_A[NG * 1024];
__device__ float g_bufA[(size_t)NN * 312];     // used as uint32[NN*156] packed
__device__ float g_bufB[(size_t)NN * 312];     // used as uint32[NN*156] packed
__device__ float g_pool[NG * 312];             // used as uint32[NG*156]
__device__ float g_t512[NG * 512];             // used as uint32[NG*256]
__device__ float g_t256[NG * 256];             // used as uint32[NG*128] or float
__device__ float g_g1[NG * 128];
__device__ float g_g2[NG * 128];
__device__ float g_cell[NG * 128];
__device__ float g_xc[NG * 384];               // used as uint32[NG*192]
__device__ uint32_t g_cellp[(size_t)NG * 500];
__device__ uint32_t g_wp[536774];

// weight-pack offsets in g_wp (word = packed k-pair x col)
#define O_W1  0
#define O_W2  3042
#define O_W3  9126
#define O_Wg1 33462
#define O_Wg2 57798
#define O_Wr1 67782
#define O_Wr2 323782
#define O_Wr3 389318
#define O_Wf1 405702
#define O_Wf2 504006

// ---------------- helpers ----------------
__device__ __forceinline__ uint32_t pack_h(float v0, float v1) {
    __half2 h = __floats2half2_rn(v0, v1);
    return *reinterpret_cast<uint32_t*>(&h);
}

__device__ __forceinline__ void mma16(float* c, const uint32_t* a, const uint32_t* b) {
    asm volatile(
        "mma.sync.aligned.m16n8k16.row.col.f32.f16.f16.f32 "
        "{%0,%1,%2,%3}, {%4,%5,%6,%7}, {%8,%9}, {%0,%1,%2,%3};"
        : "+f"(c[0]), "+f"(c[1]), "+f"(c[2]), "+f"(c[3])
        : "r"(a[0]), "r"(a[1]), "r"(a[2]), "r"(a[3]), "r"(b[0]), "r"(b[1]));
}

// ---------------- fused weight pack: all 10 weights in one launch ----------------
struct PJ { const float* W; int Kp, M; int off; };
struct PJs { PJ j[10]; int total; };

__global__ void packAll_kernel(PJs js, uint32_t* __restrict__ out) {
    int t = blockIdx.x * blockDim.x + threadIdx.x;
    if (t >= js.total) return;
#pragma unroll
    for (int i = 0; i < 10; i++) {
        int n = js.j[i].Kp * js.j[i].M;
        if (t < n) {
            int M = js.j[i].M;
            int kp = t / M, c = t - kp * M;
            const float* W = js.j[i].W;
            out[js.j[i].off + t] = pack_h(W[(size_t)(2 * kp) * M + c],
                                          W[(size_t)(2 * kp + 1) * M + c]);
            return;
        }
        t -= n;
    }
}

// X[N,K] float -> Xp[N, K/2] packed fp16x2
__global__ void packX_kernel(const float* __restrict__ X, uint32_t* __restrict__ out,
                             int N, int K) {
    int Kp = K >> 1;
    int idx = blockIdx.x * blockDim.x + threadIdx.x;
    if (idx >= N * Kp) return;
    int row = idx / Kp, p = idx - row * Kp;
    out[idx] = pack_h(X[(size_t)row * K + 2 * p], X[(size_t)row * K + 2 * p + 1]);
}

// ---------------- build per-graph normalized adjacency ----------------
__global__ void build_A_kernel(const int* __restrict__ ei, float* __restrict__ A) {
    __shared__ int   deg[32];
    __shared__ float dinv[32];
    __shared__ float cnt[1024];
    int g = blockIdx.x, t = threadIdx.x;
    if (t < 32) deg[t] = 1;
    for (int i = t; i < 1024; i += 128) cnt[i] = 0.f;
    __syncthreads();
    int src = ei[g * EPG + t] & 31;
    int dst = ei[NE + g * EPG + t] & 31;
    atomicAdd(&deg[src], 1);
    __syncthreads();
    if (t < 32) dinv[t] = rsqrtf((float)deg[t]);
    atomicAdd(&cnt[src * 32 + dst], 1.f);
    __syncthreads();
    for (int i = t; i < 1024; i += 128) {
        int r = i >> 5, c = i & 31;
        float v = cnt[i] + (r == c ? 1.f : 0.f);
        A[g * 1024 + i] = v * dinv[r] * dinv[c];
    }
}

// ================= pure-fp16 GEMM on packed inputs =================
// Xp: [N, Kp] uint32 (fp16x2 of k-pair); Wp: [Kp, M] uint32 (fp16x2 of k-pair per col).
// block tile 128x128, 512 threads / 16 warps (4x4), warp tile 32x32, fp32 accum.
// POOL=1: relu+bias then per-graph (32-row) max -> packed pairs; OPACK=1: packed col-pair out.
template <int ACT, int OPACK, int POOL>
__global__ void __launch_bounds__(512)
gemm_h_kernel(const uint32_t* __restrict__ Xp, const uint32_t* __restrict__ Wp,
              const float* __restrict__ bias, void* __restrict__ Cv,
              int N, int Kp, int M, const float* __restrict__ pa) {
    __shared__ uint32_t As[2][128 * AST];
    __shared__ uint32_t Bs[2][16 * BST];
    int tid = threadIdx.x, lane = tid & 31, w = tid >> 5;
    int wm = w & 3, wn = w >> 2;
    int gid = lane >> 2, tig = lane & 3;
    int R0 = blockIdx.y * 128, C0 = blockIdx.x * 128;
    float acc[2][4][4] = {};
    int NC = (Kp + 15) >> 4;

    auto stage = [&](int chunk, int buf) {
        int kp0 = chunk * 16;
#pragma unroll
        for (int it = 0; it < 4; it++) {            // A: 128 rows x 16 kpairs, 4B each
            int i = tid + it * 512;
            int row = i >> 4, kpl = i & 15;
            int kp = kp0 + kpl;
            const uint32_t* src = Xp + (size_t)(R0 + row) * Kp + (kp < Kp ? kp : 0);
            uint32_t ss = (kp < Kp) ? 4u : 0u;
            uint32_t dst = (uint32_t)__cvta_generic_to_shared(&As[buf][row * AST + kpl]);
            asm volatile("cp.async.ca.shared.global [%0], [%1], 4, %2;"
                         :: "r"(dst), "l"(src), "r"(ss));
        }
#pragma unroll
        for (int it = 0; it < 2; it++) {            // B: 16 kpairs x 128 cols, 8B each
            int i = tid + it * 512;
            int c2 = i & 63, kpl = i >> 6;
            int kp = kp0 + kpl, col = 2 * c2;
            bool ok = (kp < Kp) && (C0 + col < M);
            const uint32_t* src = Wp + (ok ? ((size_t)kp * M + C0 + col) : 0);
            uint32_t ss = ok ? 8u : 0u;
            uint32_t dst = (uint32_t)__cvta_generic_to_shared(&Bs[buf][kpl * BST + col]);
            asm volatile("cp.async.ca.shared.global [%0], [%1], 8, %2;"
                         :: "r"(dst), "l"(src), "r"(ss));
        }
        asm volatile("cp.async.commit_group;");
    };

    stage(0, 0);
    for (int ch = 0; ch < NC; ch++) {
        int buf = ch & 1;
        if (ch + 1 < NC) {
            stage(ch + 1, buf ^ 1);
            asm volatile("cp.async.wait_group 1;");
        } else {
            asm volatile("cp.async.wait_group 0;");
        }
        __syncthreads();
        const uint32_t* Ab = As[buf];
        const uint32_t* Bb = Bs[buf];
#pragma unroll
        for (int s = 0; s < 2; s++) {
            int p = s * 8 + tig;
            uint32_t a[2][4], b[4][2];
#pragma unroll
            for (int mt = 0; mt < 2; mt++) {
                int r = wm * 32 + mt * 16 + gid;
                a[mt][0] = Ab[r * AST + p];
                a[mt][1] = Ab[(r + 8) * AST + p];
                a[mt][2] = Ab[r * AST + p + 4];
                a[mt][3] = Ab[(r + 8) * AST + p + 4];
            }
#pragma unroll
            for (int nt = 0; nt < 4; nt++) {
                int c = wn * 32 + nt * 8 + gid;
                b[nt][0] = Bb[p * BST + c];
                b[nt][1] = Bb[(p + 4) * BST + c];
            }
#pragma unroll
            for (int mt = 0; mt < 2; mt++)
#pragma unroll
                for (int nt = 0; nt < 4; nt++)
                    mma16(acc[mt][nt], a[mt], b[nt]);
        }
        __syncthreads();
    }

    float alpha = (ACT == 2) ? *pa : 0.f;
    if (POOL) {
        float mx[4][2];
#pragma unroll
        for (int nt = 0; nt < 4; nt++) { mx[nt][0] = -3.4e38f; mx[nt][1] = -3.4e38f; }
#pragma unroll
        for (int nt = 0; nt < 4; nt++)
#pragma unroll
            for (int q1 = 0; q1 < 2; q1++) {
                int col = C0 + wn * 32 + nt * 8 + 2 * tig + q1;
                float b = (col < M) ? bias[col] : 0.f;
#pragma unroll
                for (int mt = 0; mt < 2; mt++)
#pragma unroll
                    for (int qh = 0; qh < 2; qh++)
                        mx[nt][q1] = fmaxf(mx[nt][q1], fmaxf(acc[mt][nt][qh * 2 + q1] + b, 0.f));
            }
#pragma unroll
        for (int o = 4; o < 32; o <<= 1)
#pragma unroll
            for (int nt = 0; nt < 4; nt++) {
                mx[nt][0] = fmaxf(mx[nt][0], __shfl_xor_sync(0xffffffffu, mx[nt][0], o));
                mx[nt][1] = fmaxf(mx[nt][1], __shfl_xor_sync(0xffffffffu, mx[nt][1], o));
            }
        if (gid == 0) {
            int graph = (R0 >> 5) + wm;
            uint32_t* Cp = (uint32_t*)Cv;
#pragma unroll
            for (int nt = 0; nt < 4; nt++) {
                int c = C0 + wn * 32 + nt * 8 + 2 * tig;
                if (c < M)
                    Cp[(size_t)graph * (M >> 1) + (c >> 1)] = pack_h(mx[nt][0], mx[nt][1]);
            }
        }
    } else if (OPACK) {
        uint32_t* Cp = (uint32_t*)Cv;
#pragma unroll
        for (int mt = 0; mt < 2; mt++)
#pragma unroll
            for (int nt = 0; nt < 4; nt++) {
                int row = R0 + wm * 32 + mt * 16 + gid;
                int c = C0 + wn * 32 + nt * 8 + 2 * tig;
                if (c < M) {
                    float b0 = bias[c], b1 = bias[c + 1];
                    float v0 = acc[mt][nt][0] + b0, v1 = acc[mt][nt][1] + b1;
                    float v2 = acc[mt][nt][2] + b0, v3 = acc[mt][nt][3] + b1;
                    if (ACT == 1) {
                        v0 = fmaxf(v0, 0.f); v1 = fmaxf(v1, 0.f);
                        v2 = fmaxf(v2, 0.f); v3 = fmaxf(v3, 0.f);
                    }
                    if (ACT == 2) {
                        v0 = (v0 >= 0.f) ? v0 : alpha * v0;
                        v1 = (v1 >= 0.f) ? v1 : alpha * v1;
                        v2 = (v2 >= 0.f) ? v2 : alpha * v2;
                        v3 = (v3 >= 0.f) ? v3 : alpha * v3;
                    }
                    Cp[(size_t)row * (M >> 1) + (c >> 1)]       = pack_h(v0, v1);
                    Cp[(size_t)(row + 8) * (M >> 1) + (c >> 1)] = pack_h(v2, v3);
                }
            }
    } else {
        float* Cf = (float*)Cv;
#pragma unroll
        for (int mt = 0; mt < 2; mt++)
#pragma unroll
            for (int nt = 0; nt < 4; nt++) {
                int row = R0 + wm * 32 + mt * 16 + gid;
                int col = C0 + wn * 32 + nt * 8 + 2 * tig;
#pragma unroll
                for (int q = 0; q < 4; q++) {
                    int r = row + (q >> 1) * 8;
                    int c = col + (q & 1);
                    if (c < M) {
                        float v = acc[mt][nt][q] + (bias ? bias[c] : 0.f);
                        if (ACT == 1) v = fmaxf(v, 0.f);
                        if (ACT == 2) v = (v >= 0.f) ? v : alpha * v;
                        Cf[(size_t)r * M + c] = v;
                    }
                }
            }
    }
}

// ================= pure-fp16 propagation: P_g = A_g (32x32) @ X_g (32xK) =================
// FLOATIN=1: X is float [32, K]; else packed uint32 [32, Kp] (feature pairs).
// Output P: packed uint32 [32, Kp]. 1 block/graph, 4 warps; warp owns 16-feat slice of 64-chunk.
template <int FLOATIN>
__global__ void __launch_bounds__(128)
prop_h_kernel(const float* __restrict__ A, const void* __restrict__ Xin,
              uint32_t* __restrict__ P, int K) {
    __shared__ uint32_t sAh[32 * PST];
    __shared__ uint32_t sXw[64 * PST];            // half[64 feats][40 nodes+pad]
    int g = blockIdx.x, tid = threadIdx.x, lane = tid & 31, w = tid >> 5;
    int gid = lane >> 2, tig = lane & 3;
    int Kp = K >> 1;
    const float* Ag = A + g * 1024;
#pragma unroll
    for (int it = 0; it < 4; it++) {              // stage A: 32 rows x 16 node-pairs
        int i = tid + it * 128;
        int r = i >> 4, kp = i & 15;
        sAh[r * PST + kp] = pack_h(Ag[r * 32 + 2 * kp], Ag[r * 32 + 2 * kp + 1]);
    }
    __syncthreads();
    uint32_t a[2][2][4];                           // [s][mt][frag]
#pragma unroll
    for (int s = 0; s < 2; s++)
#pragma unroll
        for (int mt = 0; mt < 2; mt++) {
            int r = mt * 16 + gid;
            int p = s * 8 + tig;
            a[s][mt][0] = sAh[r * PST + p];
            a[s][mt][1] = sAh[(r + 8) * PST + p];
            a[s][mt][2] = sAh[r * PST + p + 4];
            a[s][mt][3] = sAh[(r + 8) * PST + p + 4];
        }
    const float*    Xf = (const float*)Xin;
    const uint32_t* Xp = (const uint32_t*)Xin;
    __half* sXh = (__half*)sXw;
    uint32_t* Pg = P + (size_t)g * 32 * Kp;
    for (int f0 = 0; f0 < Kp; f0 += 32) {          // 32 fpairs = 64 feats per chunk
        if (f0) __syncthreads();
#pragma unroll
        for (int it = 0; it < 8; it++) {           // stage X: 32 nodes x 32 fpairs
            int i = tid + it * 128;
            int c = i & 31, fp = i >> 5;
            int f = f0 + fp;
            __half h0, h1;
            if (f < Kp) {
                if (FLOATIN) {
                    __half2 h = __floats2half2_rn(Xf[(size_t)g * 32 * K + c * K + 2 * f],
                                                  Xf[(size_t)g * 32 * K + c * K + 2 * f + 1]);
                    h0 = __low2half(h); h1 = __high2half(h);
                } else {
                    uint32_t v = Xp[(size_t)g * 32 * Kp + c * Kp + f];
                    __half2 h = *reinterpret_cast<__half2*>(&v);
                    h0 = __low2half(h); h1 = __high2half(h);
                }
            } else {
                h0 = __ushort_as_half(0); h1 = __ushort_as_half(0);
            }
            sXh[(2 * fp) * (2 * PST) + c]     = h0;
            sXh[(2 * fp + 1) * (2 * PST) + c] = h1;
        }
        __syncthreads();
        float acc[2][2][4] = {};
#pragma unroll
        for (int s = 0; s < 2; s++) {
            int p = s * 8 + tig;
            uint32_t b[2][2];
#pragma unroll
            for (int nt = 0; nt < 2; nt++) {
                int f = w * 16 + nt * 8 + gid;     // local feature index (0..63)
                b[nt][0] = sXw[f * PST + p];
                b[nt][1] = sXw[f * PST + p + 4];
            }
#pragma unroll
            for (int mt = 0; mt < 2; mt++)
#pragma unroll
                for (int nt = 0; nt < 2; nt++)
                    mma16(acc[mt][nt], a[s][mt], b[nt]);
        }
#pragma unroll
        for (int mt = 0; mt < 2; mt++)
#pragma unroll
            for (int nt = 0; nt < 2; nt++) {
                int row = mt * 16 + gid;
                int pair = f0 + w * 8 + nt * 4 + tig;
                if (pair < Kp) {
                    Pg[(size_t)row * Kp + pair]       = pack_h(acc[mt][nt][0], acc[mt][nt][1]);
                    Pg[(size_t)(row + 8) * Kp + pair] = pack_h(acc[mt][nt][2], acc[mt][nt][3]);
                }
            }
    }
}

// ---------------- concat [g1,g2,c] + L2 normalize -> packed pairs ----------------
__global__ void catnorm_kernel(const float* __restrict__ g1, const float* __restrict__ g2,
                               const float* __restrict__ c, uint32_t* __restrict__ xcp) {
    int g = blockIdx.x, t = threadIdx.x;   // 192 threads, pair (2t, 2t+1) of the 384 concat
    const float* src = (t < 64) ? (g1 + g * 128) : (t < 128 ? (g2 + g * 128) : (c + g * 128));
    int off = (t & 63) * 2;
    float a0 = src[off], a1 = src[off + 1];
    float ps = a0 * a0 + a1 * a1;
    __shared__ float red[6];
#pragma unroll
    for (int o = 16; o; o >>= 1) ps += __shfl_xor_sync(0xffffffffu, ps, o);
    if ((t & 31) == 0) red[t >> 5] = ps;
    __syncthreads();
    float tot = red[0] + red[1] + red[2] + red[3] + red[4] + red[5];
    float inv = 1.f / fmaxf(sqrtf(tot), 1e-12f);
    xcp[g * 192 + t] = pack_h(a0 * inv, a1 * inv);
}

// ---------------- final: sigmoid(x @ Wo + bo) ----------------
__global__ void final_kernel(const float* __restrict__ x, const float* __restrict__ Wo,
                             const float* __restrict__ bo, float* __restrict__ out) {
    int w = (blockIdx.x * blockDim.x + threadIdx.x) >> 5;
    int lane = threadIdx.x & 31;
    if (w >= NG) return;
    float acc = 0.f;
#pragma unroll
    for (int k = lane; k < 128; k += 32) acc = fmaf(x[w * 128 + k], Wo[k], acc);
#pragma unroll
    for (int o = 16; o; o >>= 1) acc += __shfl_xor_sync(0xffffffffu, acc, o);
    if (lane == 0) out[w] = 1.f / (1.f + expf(-(acc + bo[0])));
}

// ---------------- host side ----------------
static void gemm_launch(const uint32_t* Xp, const uint32_t* Wp, const float* bias, void* C,
                        int N, int Kp, int M, int act, int opack, int pool, const float* pa) {
    dim3 grid((M + 127) / 128, N / 128);
    if (pool)
        gemm_h_kernel<1, 1, 1><<<grid, 512>>>(Xp, Wp, bias, C, N, Kp, M, nullptr);
    else if (act == 1 && opack)
        gemm_h_kernel<1, 1, 0><<<grid, 512>>>(Xp, Wp, bias, C, N, Kp, M, nullptr);
    else if (act == 0)
        gemm_h_kernel<0, 0, 0><<<grid, 512>>>(Xp, Wp, bias, C, N, Kp, M, nullptr);
    else if (act == 2 && opack)
        gemm_h_kernel<2, 1, 0><<<grid, 512>>>(Xp, Wp, bias, C, N, Kp, M, pa);
    else
        gemm_h_kernel<2, 0, 0><<<grid, 512>>>(Xp, Wp, bias, C, N, Kp, M, pa);
}

extern "C" void kernel_launch(void* const* d_in, const int* in_sizes, int n_in,
                              void* d_out, int out_size) {
    const float* x1   = (const float*)d_in[0];
    const int*   ei1  = (const int*)d_in[1];
    const float* x2   = (const float*)d_in[2];
    const int*   ei2  = (const int*)d_in[3];
    const float* cell = (const float*)d_in[4];
    const float* W1  = (const float*)d_in[7],  *b1  = (const float*)d_in[8];
    const float* W2  = (const float*)d_in[9],  *b2  = (const float*)d_in[10];
    const float* W3  = (const float*)d_in[11], *b3  = (const float*)d_in[12];
    const float* Wg1 = (const float*)d_in[13], *bg1 = (const float*)d_in[14];
    const float* Wg2 = (const float*)d_in[15], *bg2 = (const float*)d_in[16];
    const float* Wr1 = (const float*)d_in[17], *br1 = (const float*)d_in[18];
    const float* Wr2 = (const float*)d_in[19], *br2 = (const float*)d_in[20];
    const float* Wr3 = (const float*)d_in[21], *br3 = (const float*)d_in[22];
    const float* Wf1 = (const float*)d_in[23], *bf1 = (const float*)d_in[24];
    const float* Wf2 = (const float*)d_in[25], *bf2 = (const float*)d_in[26];
    const float* Wo  = (const float*)d_in[27], *bo  = (const float*)d_in[28];
    const float* pa  = (const float*)d_in[29];
    float* out = (float*)d_out;

    float *A, *bufA, *bufB, *pool, *t512, *t256, *G1, *G2, *Cl, *XC;
    uint32_t *wp, *cellp;
    cudaGetSymbolAddress((void**)&A,    g_A);
    cudaGetSymbolAddress((void**)&bufA, g_bufA);
    cudaGetSymbolAddress((void**)&bufB, g_bufB);
    cudaGetSymbolAddress((void**)&pool, g_pool);
    cudaGetSymbolAddress((void**)&t512, g_t512);
    cudaGetSymbolAddress((void**)&t256, g_t256);
    cudaGetSymbolAddress((void**)&G1,   g_g1);
    cudaGetSymbolAddress((void**)&G2,   g_g2);
    cudaGetSymbolAddress((void**)&Cl,   g_cell);
    cudaGetSymbolAddress((void**)&XC,   g_xc);
    cudaGetSymbolAddress((void**)&wp,    g_wp);
    cudaGetSymbolAddress((void**)&cellp, g_cellp);
    uint32_t* pA    = (uint32_t*)bufA;
    uint32_t* pB    = (uint32_t*)bufB;
    uint32_t* poolp = (uint32_t*)pool;
    uint32_t* t512p = (uint32_t*)t512;
    uint32_t* t256p = (uint32_t*)t256;
    uint32_t* XCp   = (uint32_t*)XC;

    // ---- fused weight pack (1 launch) + cell pack ----
    PJs js;
    js.j[0] = {W1,  39,  78,  O_W1};
    js.j[1] = {W2,  39,  156, O_W2};
    js.j[2] = {W3,  78,  312, O_W3};
    js.j[3] = {Wg1, 156, 156, O_Wg1};
    js.j[4] = {Wg2, 78,  128, O_Wg2};
    js.j[5] = {Wr1, 500, 512, O_Wr1};
    js.j[6] = {Wr2, 256, 256, O_Wr2};
    js.j[7] = {Wr3, 128, 128, O_Wr3};
    js.j[8] = {Wf1, 192, 512, O_Wf1};
    js.j[9] = {Wf2, 256, 128, O_Wf2};
    js.total = 536774;
    packAll_kernel<<<(536774 + 255) / 256, 256>>>(js, wp);
    packX_kernel<<<(NG * 500 + 255) / 256, 256>>>(cell, cellp, NG, 1000);

    for (int d = 0; d < 2; d++) {
        const float* x  = d ? x2 : x1;
        const int*   ei = d ? ei2 : ei1;
        float*       G  = d ? G2 : G1;
        build_A_kernel<<<NG, 128>>>(ei, A);
        // GCN reordered: H = relu((A @ X) @ W + b), fully packed fp16 chain
        prop_h_kernel<1><<<NG, 128>>>(A, x, pA, 78);
        gemm_launch(pA, wp + O_W1, b1, pB, NN, 39, 78, 1, 1, 0, pa);
        prop_h_kernel<0><<<NG, 128>>>(A, pB, pA, 78);
        gemm_launch(pA, wp + O_W2, b2, pB, NN, 39, 156, 1, 1, 0, pa);
        prop_h_kernel<0><<<NG, 128>>>(A, pB, pA, 156);
        // layer 3: fused relu + per-graph max pool -> packed pool[NG x 156 pairs]
        gemm_launch(pA, wp + O_W3, b3, poolp, NN, 78, 312, 1, 1, 1, pa);
        gemm_launch(poolp, wp + O_Wg1, bg1, t512p, NG, 156, 156, 1, 1, 0, pa);
        gemm_launch(t512p, wp + O_Wg2, bg2, G,    NG, 78, 128, 0, 0, 0, pa);
    }

    // cell-line MLP
    gemm_launch(cellp, wp + O_Wr1, br1, t512p, NG, 500, 512, 1, 1, 0, pa);
    gemm_launch(t512p, wp + O_Wr2, br2, t256p, NG, 256, 256, 1, 1, 0, pa);
    gemm_launch(t256p, wp + O_Wr3, br3, Cl,    NG, 128, 128, 0, 0, 0, pa);

    // concat + L2 normalize (packed) + fused head
    catnorm_kernel<<<NG, 192>>>(G1, G2, Cl, XCp);
    gemm_launch(XCp,   wp + O_Wf1, bf1, t512p, NG, 192, 512, 2, 1, 0, pa);
    gemm_launch(t512p, wp + O_Wf2, bf2, t256,  NG, 256, 128, 2, 0, 0, pa);
    final_kernel<<<NG / 8, 256>>>(t256, Wo, bo, out);
}

// round 17
// speedup vs baseline: 5.1678x; 1.0540x over previous
#include <cuda_runtime.h>
#include <cuda_fp16.h>
#include <math.h>
#include <stdint.h>

#define NN 262144
#define NE 1048576
#define NG 8192
#define EPG 128
#define AST 20    // gemm A smem stride (words)
#define BST 136   // gemm B smem stride (words)
#define PST 20    // prop smem stride (words)

// ---------------- scratch (sanctioned __device__ globals) ----------------
__device__ uint32_t g_Ap[NG * 512];            // packed fp16 adjacency (32 x 16 pairs/graph)
__device__ float g_bufA[(size_t)NN * 312];     // used as uint32[NN*156] packed
__device__ float g_bufB[(size_t)NN * 312];     // used as uint32[NN*156] packed
__device__ float g_pool[NG * 312];             // used as uint32[NG*156]
__device__ float g_t512[NG * 512];             // used as uint32[NG*256]
__device__ float g_t256[NG * 256];             // used as uint32[NG*128] or float
__device__ float g_g1[NG * 128];
__device__ float g_g2[NG * 128];
__device__ float g_cell[NG * 128];
__device__ float g_xc[NG * 384];               // used as uint32[NG*192]
__device__ uint32_t g_cellp[(size_t)NG * 500];
__device__ uint32_t g_wp[536774];

// weight-pack offsets in g_wp (word = packed k-pair x col)
#define O_W1  0
#define O_W2  3042
#define O_W3  9126
#define O_Wg1 33462
#define O_Wg2 57798
#define O_Wr1 67782
#define O_Wr2 323782
#define O_Wr3 389318
#define O_Wf1 405702
#define O_Wf2 504006

// ---------------- helpers ----------------
__device__ __forceinline__ uint32_t pack_h(float v0, float v1) {
    __half2 h = __floats2half2_rn(v0, v1);
    return *reinterpret_cast<uint32_t*>(&h);
}

__device__ __forceinline__ void mma16(float* c, const uint32_t* a, const uint32_t* b) {
    asm volatile(
        "mma.sync.aligned.m16n8k16.row.col.f32.f16.f16.f32 "
        "{%0,%1,%2,%3}, {%4,%5,%6,%7}, {%8,%9}, {%0,%1,%2,%3};"
        : "+f"(c[0]), "+f"(c[1]), "+f"(c[2]), "+f"(c[3])
        : "r"(a[0]), "r"(a[1]), "r"(a[2]), "r"(a[3]), "r"(b[0]), "r"(b[1]));
}

// ---------------- fused weight pack: all 10 weights in one launch ----------------
struct PJ { const float* W; int Kp, M; int off; };
struct PJs { PJ j[10]; int total; };

__global__ void packAll_kernel(PJs js, uint32_t* __restrict__ out) {
    int t = blockIdx.x * blockDim.x + threadIdx.x;
    if (t >= js.total) return;
#pragma unroll
    for (int i = 0; i < 10; i++) {
        int n = js.j[i].Kp * js.j[i].M;
        if (t < n) {
            int M = js.j[i].M;
            int kp = t / M, c = t - kp * M;
            const float* W = js.j[i].W;
            out[js.j[i].off + t] = pack_h(W[(size_t)(2 * kp) * M + c],
                                          W[(size_t)(2 * kp + 1) * M + c]);
            return;
        }
        t -= n;
    }
}

__global__ void packX_kernel(const float* __restrict__ X, uint32_t* __restrict__ out,
                             int N, int K) {
    int Kp = K >> 1;
    int idx = blockIdx.x * blockDim.x + threadIdx.x;
    if (idx >= N * Kp) return;
    int row = idx / Kp, p = idx - row * Kp;
    out[idx] = pack_h(X[(size_t)row * K + 2 * p], X[(size_t)row * K + 2 * p + 1]);
}

// ---------------- build per-graph normalized adjacency (packed fp16 pairs) ----------------
__global__ void build_A_kernel(const int* __restrict__ ei, uint32_t* __restrict__ Ap) {
    __shared__ int   deg[32];
    __shared__ float dinv[32];
    __shared__ float cnt[1024];
    int g = blockIdx.x, t = threadIdx.x;
    if (t < 32) deg[t] = 1;
    for (int i = t; i < 1024; i += 128) cnt[i] = 0.f;
    __syncthreads();
    int src = ei[g * EPG + t] & 31;
    int dst = ei[NE + g * EPG + t] & 31;
    atomicAdd(&deg[src], 1);
    __syncthreads();
    if (t < 32) dinv[t] = rsqrtf((float)deg[t]);
    atomicAdd(&cnt[src * 32 + dst], 1.f);
    __syncthreads();
    for (int i = t; i < 512; i += 128) {
        int r = i >> 4, kp = i & 15;
        int c0 = 2 * kp, c1 = c0 + 1;
        float v0 = (cnt[r * 32 + c0] + (r == c0 ? 1.f : 0.f)) * dinv[r] * dinv[c0];
        float v1 = (cnt[r * 32 + c1] + (r == c1 ? 1.f : 0.f)) * dinv[r] * dinv[c1];
        Ap[g * 512 + i] = pack_h(v0, v1);
    }
}

// ================= pure-fp16 GEMM, optional fused prop / pool epilogue =================
// Xp: [N, Kp] uint32; Wp: [Kp, M] uint32. block tile 128x128, 512 thr / 16 warps, warp 32x32.
// Epilogues: POOL: relu+bias, per-graph max -> packed. PROP: relu+bias -> H, then A_g@H -> packed.
//            OPACK: packed col-pair out. else: float out.
#define SWORDS (2 * 128 * AST + 2 * 16 * BST)

template <int ACT, int OPACK, int POOL, int PROP>
__global__ void __launch_bounds__(512)
gemm_h_kernel(const uint32_t* __restrict__ Xp, const uint32_t* __restrict__ Wp,
              const float* __restrict__ bias, void* __restrict__ Cv,
              int N, int Kp, int M, const float* __restrict__ pa,
              const uint32_t* __restrict__ Ap) {
    __shared__ uint32_t S[SWORDS];
    int tid = threadIdx.x, lane = tid & 31, w = tid >> 5;
    int wm = w & 3, wn = w >> 2;
    int gid = lane >> 2, tig = lane & 3;
    int R0 = blockIdx.y * 128, C0 = blockIdx.x * 128;
    float acc[2][4][4] = {};
    int NC = (Kp + 15) >> 4;

    auto stage = [&](int chunk, int buf) {
        int kp0 = chunk * 16;
        uint32_t* Ad = S + buf * (128 * AST);
        uint32_t* Bd = S + 2 * 128 * AST + buf * (16 * BST);
#pragma unroll
        for (int it = 0; it < 4; it++) {            // A: 128 rows x 16 kpairs, 4B each
            int i = tid + it * 512;
            int row = i >> 4, kpl = i & 15;
            int kp = kp0 + kpl;
            const uint32_t* src = Xp + (size_t)(R0 + row) * Kp + (kp < Kp ? kp : 0);
            uint32_t ss = (kp < Kp) ? 4u : 0u;
            uint32_t dst = (uint32_t)__cvta_generic_to_shared(&Ad[row * AST + kpl]);
            asm volatile("cp.async.ca.shared.global [%0], [%1], 4, %2;"
                         :: "r"(dst), "l"(src), "r"(ss));
        }
#pragma unroll
        for (int it = 0; it < 2; it++) {            // B: 16 kpairs x 128 cols, 8B each
            int i = tid + it * 512;
            int c2 = i & 63, kpl = i >> 6;
            int kp = kp0 + kpl, col = 2 * c2;
            bool ok = (kp < Kp) && (C0 + col < M);
            const uint32_t* src = Wp + (ok ? ((size_t)kp * M + C0 + col) : 0);
            uint32_t ss = ok ? 8u : 0u;
            uint32_t dst = (uint32_t)__cvta_generic_to_shared(&Bd[kpl * BST + col]);
            asm volatile("cp.async.ca.shared.global [%0], [%1], 8, %2;"
                         :: "r"(dst), "l"(src), "r"(ss));
        }
        asm volatile("cp.async.commit_group;");
    };

    stage(0, 0);
    for (int ch = 0; ch < NC; ch++) {
        int buf = ch & 1;
        if (ch + 1 < NC) {
            stage(ch + 1, buf ^ 1);
            asm volatile("cp.async.wait_group 1;");
        } else {
            asm volatile("cp.async.wait_group 0;");
        }
        __syncthreads();
        const uint32_t* Ab = S + buf * (128 * AST);
        const uint32_t* Bb = S + 2 * 128 * AST + buf * (16 * BST);
#pragma unroll
        for (int s = 0; s < 2; s++) {
            int p = s * 8 + tig;
            uint32_t a[2][4], b[4][2];
#pragma unroll
            for (int mt = 0; mt < 2; mt++) {
                int r = wm * 32 + mt * 16 + gid;
                a[mt][0] = Ab[r * AST + p];
                a[mt][1] = Ab[(r + 8) * AST + p];
                a[mt][2] = Ab[r * AST + p + 4];
                a[mt][3] = Ab[(r + 8) * AST + p + 4];
            }
#pragma unroll
            for (int nt = 0; nt < 4; nt++) {
                int c = wn * 32 + nt * 8 + gid;
                b[nt][0] = Bb[p * BST + c];
                b[nt][1] = Bb[(p + 4) * BST + c];
            }
#pragma unroll
            for (int mt = 0; mt < 2; mt++)
#pragma unroll
                for (int nt = 0; nt < 4; nt++)
                    mma16(acc[mt][nt], a[mt], b[nt]);
        }
        __syncthreads();
    }

    float alpha = (ACT == 2) ? *pa : 0.f;
    if (POOL) {
        float mx[4][2];
#pragma unroll
        for (int nt = 0; nt < 4; nt++) { mx[nt][0] = -3.4e38f; mx[nt][1] = -3.4e38f; }
#pragma unroll
        for (int nt = 0; nt < 4; nt++)
#pragma unroll
            for (int q1 = 0; q1 < 2; q1++) {
                int col = C0 + wn * 32 + nt * 8 + 2 * tig + q1;
                float b = (col < M) ? bias[col] : 0.f;
#pragma unroll
                for (int mt = 0; mt < 2; mt++)
#pragma unroll
                    for (int qh = 0; qh < 2; qh++)
                        mx[nt][q1] = fmaxf(mx[nt][q1], fmaxf(acc[mt][nt][qh * 2 + q1] + b, 0.f));
            }
#pragma unroll
        for (int o = 4; o < 32; o <<= 1)
#pragma unroll
            for (int nt = 0; nt < 4; nt++) {
                mx[nt][0] = fmaxf(mx[nt][0], __shfl_xor_sync(0xffffffffu, mx[nt][0], o));
                mx[nt][1] = fmaxf(mx[nt][1], __shfl_xor_sync(0xffffffffu, mx[nt][1], o));
            }
        if (gid == 0) {
            int graph = (R0 >> 5) + wm;
            uint32_t* Cp = (uint32_t*)Cv;
#pragma unroll
            for (int nt = 0; nt < 4; nt++) {
                int c = C0 + wn * 32 + nt * 8 + 2 * tig;
                if (c < M)
                    Cp[(size_t)graph * (M >> 1) + (c >> 1)] = pack_h(mx[nt][0], mx[nt][1]);
            }
        }
    } else if (PROP) {
        // ---- fused propagation: P_g = A_g @ relu(acc + bias), warp-local 32x32x32 ----
        int graph = (R0 >> 5) + wm;
        const uint32_t* Ag = Ap + graph * 512;   // [node 32][kpair 16]
        uint32_t afr[2][2][4];
#pragma unroll
        for (int s = 0; s < 2; s++) {
            int p = s * 8 + tig;
#pragma unroll
            for (int mt = 0; mt < 2; mt++) {
                int r = mt * 16 + gid;
                afr[s][mt][0] = Ag[r * 16 + p];
                afr[s][mt][1] = Ag[(r + 8) * 16 + p];
                afr[s][mt][2] = Ag[r * 16 + p + 4];
                afr[s][mt][3] = Ag[(r + 8) * 16 + p + 4];
            }
        }
        uint32_t* Hw = S + w * 544;              // per-warp H: [node 32][fpair 16] stride 17
#pragma unroll
        for (int mt = 0; mt < 2; mt++)
#pragma unroll
            for (int nt = 0; nt < 4; nt++) {
                int c = C0 + wn * 32 + nt * 8 + 2 * tig;
                int f2 = nt * 4 + tig;
                uint32_t w0 = 0, w1 = 0;
                if (c < M) {
                    float b0 = bias[c], b1 = bias[c + 1];
                    w0 = pack_h(fmaxf(acc[mt][nt][0] + b0, 0.f), fmaxf(acc[mt][nt][1] + b1, 0.f));
                    w1 = pack_h(fmaxf(acc[mt][nt][2] + b0, 0.f), fmaxf(acc[mt][nt][3] + b1, 0.f));
                }
                Hw[(mt * 16 + gid) * 17 + f2]     = w0;
                Hw[(mt * 16 + gid + 8) * 17 + f2] = w1;
            }
        __syncwarp();
        float pacc[2][4][4] = {};
        const __half* Hh = (const __half*)Hw;    // stride 34 halves per node row
#pragma unroll
        for (int s = 0; s < 2; s++) {
            int p = s * 8 + tig;
            uint32_t b[4][2];
#pragma unroll
            for (int nt = 0; nt < 4; nt++) {
                int f = nt * 8 + gid;
                __half2 lo = __halves2half2(Hh[(2 * p) * 34 + f],     Hh[(2 * p + 1) * 34 + f]);
                __half2 hi = __halves2half2(Hh[(2 * p + 8) * 34 + f], Hh[(2 * p + 9) * 34 + f]);
                b[nt][0] = *reinterpret_cast<uint32_t*>(&lo);
                b[nt][1] = *reinterpret_cast<uint32_t*>(&hi);
            }
#pragma unroll
            for (int mt = 0; mt < 2; mt++)
#pragma unroll
                for (int nt = 0; nt < 4; nt++)
                    mma16(pacc[mt][nt], afr[s][mt], b[nt]);
        }
        uint32_t* Cp = (uint32_t*)Cv;
        int Mp = M >> 1;
#pragma unroll
        for (int mt = 0; mt < 2; mt++)
#pragma unroll
            for (int nt = 0; nt < 4; nt++) {
                int row = R0 + wm * 32 + mt * 16 + gid;
                int c = C0 + wn * 32 + nt * 8 + 2 * tig;
                if (c < M) {
                    Cp[(size_t)row * Mp + (c >> 1)]       = pack_h(pacc[mt][nt][0], pacc[mt][nt][1]);
                    Cp[(size_t)(row + 8) * Mp + (c >> 1)] = pack_h(pacc[mt][nt][2], pacc[mt][nt][3]);
                }
            }
    } else if (OPACK) {
        uint32_t* Cp = (uint32_t*)Cv;
#pragma unroll
        for (int mt = 0; mt < 2; mt++)
#pragma unroll
            for (int nt = 0; nt < 4; nt++) {
                int row = R0 + wm * 32 + mt * 16 + gid;
                int c = C0 + wn * 32 + nt * 8 + 2 * tig;
                if (c < M) {
                    float b0 = bias[c], b1 = bias[c + 1];
                    float v0 = acc[mt][nt][0] + b0, v1 = acc[mt][nt][1] + b1;
                    float v2 = acc[mt][nt][2] + b0, v3 = acc[mt][nt][3] + b1;
                    if (ACT == 1) {
                        v0 = fmaxf(v0, 0.f); v1 = fmaxf(v1, 0.f);
                        v2 = fmaxf(v2, 0.f); v3 = fmaxf(v3, 0.f);
                    }
                    if (ACT == 2) {
                        v0 = (v0 >= 0.f) ? v0 : alpha * v0;
                        v1 = (v1 >= 0.f) ? v1 : alpha * v1;
                        v2 = (v2 >= 0.f) ? v2 : alpha * v2;
                        v3 = (v3 >= 0.f) ? v3 : alpha * v3;
                    }
                    Cp[(size_t)row * (M >> 1) + (c >> 1)]       = pack_h(v0, v1);
                    Cp[(size_t)(row + 8) * (M >> 1) + (c >> 1)] = pack_h(v2, v3);
                }
            }
    } else {
        float* Cf = (float*)Cv;
#pragma unroll
        for (int mt = 0; mt < 2; mt++)
#pragma unroll
            for (int nt = 0; nt < 4; nt++) {
                int row = R0 + wm * 32 + mt * 16 + gid;
                int col = C0 + wn * 32 + nt * 8 + 2 * tig;
#pragma unroll
                for (int q = 0; q < 4; q++) {
                    int r = row + (q >> 1) * 8;
                    int c = col + (q & 1);
                    if (c < M) {
                        float v = acc[mt][nt][q] + (bias ? bias[c] : 0.f);
                        if (ACT == 1) v = fmaxf(v, 0.f);
                        if (ACT == 2) v = (v >= 0.f) ? v : alpha * v;
                        Cf[(size_t)r * M + c] = v;
                    }
                }
            }
    }
}

// ================= first propagation: P_g = A_g @ X_g (float X input) =================
__global__ void __launch_bounds__(128)
prop_h_kernel(const uint32_t* __restrict__ Ap, const float* __restrict__ Xf,
              uint32_t* __restrict__ P, int K) {
    __shared__ uint32_t sAh[32 * PST];
    __shared__ uint32_t sXw[64 * PST];
    int g = blockIdx.x, tid = threadIdx.x, lane = tid & 31, w = tid >> 5;
    int gid = lane >> 2, tig = lane & 3;
    int Kp = K >> 1;
    for (int i = tid; i < 512; i += 128) {
        int r = i >> 4, kp = i & 15;
        sAh[r * PST + kp] = Ap[g * 512 + i];
    }
    __syncthreads();
    uint32_t a[2][2][4];
#pragma unroll
    for (int s = 0; s < 2; s++)
#pragma unroll
        for (int mt = 0; mt < 2; mt++) {
            int r = mt * 16 + gid;
            int p = s * 8 + tig;
            a[s][mt][0] = sAh[r * PST + p];
            a[s][mt][1] = sAh[(r + 8) * PST + p];
            a[s][mt][2] = sAh[r * PST + p + 4];
            a[s][mt][3] = sAh[(r + 8) * PST + p + 4];
        }
    __half* sXh = (__half*)sXw;
    uint32_t* Pg = P + (size_t)g * 32 * Kp;
    for (int f0 = 0; f0 < Kp; f0 += 32) {
        if (f0) __syncthreads();
#pragma unroll
        for (int it = 0; it < 8; it++) {
            int i = tid + it * 128;
            int c = i & 31, fp = i >> 5;
            int f = f0 + fp;
            __half h0 = __ushort_as_half(0), h1 = __ushort_as_half(0);
            if (f < Kp) {
                __half2 h = __floats2half2_rn(Xf[(size_t)g * 32 * K + c * K + 2 * f],
                                              Xf[(size_t)g * 32 * K + c * K + 2 * f + 1]);
                h0 = __low2half(h); h1 = __high2half(h);
            }
            sXh[(2 * fp) * (2 * PST) + c]     = h0;
            sXh[(2 * fp + 1) * (2 * PST) + c] = h1;
        }
        __syncthreads();
        float acc[2][2][4] = {};
#pragma unroll
        for (int s = 0; s < 2; s++) {
            int p = s * 8 + tig;
            uint32_t b[2][2];
#pragma unroll
            for (int nt = 0; nt < 2; nt++) {
                int f = w * 16 + nt * 8 + gid;
                b[nt][0] = sXw[f * PST + p];
                b[nt][1] = sXw[f * PST + p + 4];
            }
#pragma unroll
            for (int mt = 0; mt < 2; mt++)
#pragma unroll
                for (int nt = 0; nt < 2; nt++)
                    mma16(acc[mt][nt], a[s][mt], b[nt]);
        }
#pragma unroll
        for (int mt = 0; mt < 2; mt++)
#pragma unroll
            for (int nt = 0; nt < 2; nt++) {
                int row = mt * 16 + gid;
                int pair = f0 + w * 8 + nt * 4 + tig;
                if (pair < Kp) {
                    Pg[(size_t)row * Kp + pair]       = pack_h(acc[mt][nt][0], acc[mt][nt][1]);
                    Pg[(size_t)(row + 8) * Kp + pair] = pack_h(acc[mt][nt][2], acc[mt][nt][3]);
                }
            }
    }
}

// ---------------- concat [g1,g2,c] + L2 normalize -> packed pairs ----------------
__global__ void catnorm_kernel(const float* __restrict__ g1, const float* __restrict__ g2,
                               const float* __restrict__ c, uint32_t* __restrict__ xcp) {
    int g = blockIdx.x, t = threadIdx.x;
    const float* src = (t < 64) ? (g1 + g * 128) : (t < 128 ? (g2 + g * 128) : (c + g * 128));
    int off = (t & 63) * 2;
    float a0 = src[off], a1 = src[off + 1];
    float ps = a0 * a0 + a1 * a1;
    __shared__ float red[6];
#pragma unroll
    for (int o = 16; o; o >>= 1) ps += __shfl_xor_sync(0xffffffffu, ps, o);
    if ((t & 31) == 0) red[t >> 5] = ps;
    __syncthreads();
    float tot = red[0] + red[1] + red[2] + red[3] + red[4] + red[5];
    float inv = 1.f / fmaxf(sqrtf(tot), 1e-12f);
    xcp[g * 192 + t] = pack_h(a0 * inv, a1 * inv);
}

// ---------------- final: sigmoid(x @ Wo + bo) ----------------
__global__ void final_kernel(const float* __restrict__ x, const float* __restrict__ Wo,
                             const float* __restrict__ bo, float* __restrict__ out) {
    int w = (blockIdx.x * blockDim.x + threadIdx.x) >> 5;
    int lane = threadIdx.x & 31;
    if (w >= NG) return;
    float acc = 0.f;
#pragma unroll
    for (int k = lane; k < 128; k += 32) acc = fmaf(x[w * 128 + k], Wo[k], acc);
#pragma unroll
    for (int o = 16; o; o >>= 1) acc += __shfl_xor_sync(0xffffffffu, acc, o);
    if (lane == 0) out[w] = 1.f / (1.f + expf(-(acc + bo[0])));
}

// ---------------- host side ----------------
static void gemm_launch(const uint32_t* Xp, const uint32_t* Wp, const float* bias, void* C,
                        int N, int Kp, int M, int act, int opack, int pool, int prop,
                        const float* pa, const uint32_t* Ap) {
    dim3 grid((M + 127) / 128, N / 128);
    if (prop)
        gemm_h_kernel<1, 0, 0, 1><<<grid, 512>>>(Xp, Wp, bias, C, N, Kp, M, nullptr, Ap);
    else if (pool)
        gemm_h_kernel<1, 1, 1, 0><<<grid, 512>>>(Xp, Wp, bias, C, N, Kp, M, nullptr, nullptr);
    else if (act == 1 && opack)
        gemm_h_kernel<1, 1, 0, 0><<<grid, 512>>>(Xp, Wp, bias, C, N, Kp, M, nullptr, nullptr);
    else if (act == 0)
        gemm_h_kernel<0, 0, 0, 0><<<grid, 512>>>(Xp, Wp, bias, C, N, Kp, M, nullptr, nullptr);
    else if (act == 2 && opack)
        gemm_h_kernel<2, 1, 0, 0><<<grid, 512>>>(Xp, Wp, bias, C, N, Kp, M, pa, nullptr);
    else
        gemm_h_kernel<2, 0, 0, 0><<<grid, 512>>>(Xp, Wp, bias, C, N, Kp, M, pa, nullptr);
}

extern "C" void kernel_launch(void* const* d_in, const int* in_sizes, int n_in,
                              void* d_out, int out_size) {
    const float* x1   = (const float*)d_in[0];
    const int*   ei1  = (const int*)d_in[1];
    const float* x2   = (const float*)d_in[2];
    const int*   ei2  = (const int*)d_in[3];
    const float* cell = (const float*)d_in[4];
    const float* W1  = (const float*)d_in[7],  *b1  = (const float*)d_in[8];
    const float* W2  = (const float*)d_in[9],  *b2  = (const float*)d_in[10];
    const float* W3  = (const float*)d_in[11], *b3  = (const float*)d_in[12];
    const float* Wg1 = (const float*)d_in[13], *bg1 = (const float*)d_in[14];
    const float* Wg2 = (const float*)d_in[15], *bg2 = (const float*)d_in[16];
    const float* Wr1 = (const float*)d_in[17], *br1 = (const float*)d_in[18];
    const float* Wr2 = (const float*)d_in[19], *br2 = (const float*)d_in[20];
    const float* Wr3 = (const float*)d_in[21], *br3 = (const float*)d_in[22];
    const float* Wf1 = (const float*)d_in[23], *bf1 = (const float*)d_in[24];
    const float* Wf2 = (const float*)d_in[25], *bf2 = (const float*)d_in[26];
    const float* Wo  = (const float*)d_in[27], *bo  = (const float*)d_in[28];
    const float* pa  = (const float*)d_in[29];
    float* out = (float*)d_out;

    float *bufA, *bufB, *pool, *t512, *t256, *G1, *G2, *Cl, *XC;
    uint32_t *Ap, *wp, *cellp;
    cudaGetSymbolAddress((void**)&Ap,   g_Ap);
    cudaGetSymbolAddress((void**)&bufA, g_bufA);
    cudaGetSymbolAddress((void**)&bufB, g_bufB);
    cudaGetSymbolAddress((void**)&pool, g_pool);
    cudaGetSymbolAddress((void**)&t512, g_t512);
    cudaGetSymbolAddress((void**)&t256, g_t256);
    cudaGetSymbolAddress((void**)&G1,   g_g1);
    cudaGetSymbolAddress((void**)&G2,   g_g2);
    cudaGetSymbolAddress((void**)&Cl,   g_cell);
    cudaGetSymbolAddress((void**)&XC,   g_xc);
    cudaGetSymbolAddress((void**)&wp,    g_wp);
    cudaGetSymbolAddress((void**)&cellp, g_cellp);
    uint32_t* pA    = (uint32_t*)bufA;
    uint32_t* pB    = (uint32_t*)bufB;
    uint32_t* poolp = (uint32_t*)pool;
    uint32_t* t512p = (uint32_t*)t512;
    uint32_t* t256p = (uint32_t*)t256;
    uint32_t* XCp   = (uint32_t*)XC;

    // ---- fused weight pack (1 launch) + cell pack ----
    PJs js;
    js.j[0] = {W1,  39,  78,  O_W1};
    js.j[1] = {W2,  39,  156, O_W2};
    js.j[2] = {W3,  78,  312, O_W3};
    js.j[3] = {Wg1, 156, 156, O_Wg1};
    js.j[4] = {Wg2, 78,  128, O_Wg2};
    js.j[5] = {Wr1, 500, 512, O_Wr1};
    js.j[6] = {Wr2, 256, 256, O_Wr2};
    js.j[7] = {Wr3, 128, 128, O_Wr3};
    js.j[8] = {Wf1, 192, 512, O_Wf1};
    js.j[9] = {Wf2, 256, 128, O_Wf2};
    js.total = 536774;
    packAll_kernel<<<(536774 + 255) / 256, 256>>>(js, wp);
    packX_kernel<<<(NG * 500 + 255) / 256, 256>>>(cell, cellp, NG, 1000);

    for (int d = 0; d < 2; d++) {
        const float* x  = d ? x2 : x1;
        const int*   ei = d ? ei2 : ei1;
        float*       G  = d ? G2 : G1;
        build_A_kernel<<<NG, 128>>>(ei, Ap);
        // P1 = A @ X
        prop_h_kernel<<<NG, 128>>>(Ap, x, pA, 78);
        // layer1 GEMM + fused prop: out = A @ relu(P1 W1 + b1)
        gemm_launch(pA, wp + O_W1, b1, pB, NN, 39, 78, 1, 0, 0, 1, pa, Ap);
        // layer2 GEMM + fused prop
        gemm_launch(pB, wp + O_W2, b2, pA, NN, 39, 156, 1, 0, 0, 1, pa, Ap);
        // layer3 GEMM + fused relu + per-graph max pool
        gemm_launch(pA, wp + O_W3, b3, poolp, NN, 78, 312, 1, 1, 1, 0, pa, nullptr);
        gemm_launch(poolp, wp + O_Wg1, bg1, t512p, NG, 156, 156, 1, 1, 0, 0, pa, nullptr);
        gemm_launch(t512p, wp + O_Wg2, bg2, G,    NG, 78, 128, 0, 0, 0, 0, pa, nullptr);
    }

    // cell-line MLP
    gemm_launch(cellp, wp + O_Wr1, br1, t512p, NG, 500, 512, 1, 1, 0, 0, pa, nullptr);
    gemm_launch(t512p, wp + O_Wr2, br2, t256p, NG, 256, 256, 1, 1, 0, 0, pa, nullptr);
    gemm_launch(t256p, wp + O_Wr3, br3, Cl,    NG, 128, 128, 0, 0, 0, 0, pa, nullptr);

    // concat + L2 normalize (packed) + fused head
    catnorm_kernel<<<NG, 192>>>(G1, G2, Cl, XCp);
    gemm_launch(XCp,   wp + O_Wf1, bf1, t512p, NG, 192, 512, 2, 1, 0, 0, pa, nullptr);
    gemm_launch(t512p, wp + O_Wf2, bf2, t256,  NG, 256, 128, 2, 0, 0, 0, pa, nullptr);
    final_kernel<<<NG / 8, 256>>>(t256, Wo, bo, out);
}